// round 6
// baseline (speedup 1.0000x reference)
#include <cuda_runtime.h>
#include <math.h>
#include <stdint.h>

// GraphRNN: 2-layer LayerNorm-GRU scan. B=16, T=24, N=207, D=512, G=1536.
// R6: 128x64 tiles @ 3 CTAs/SM (24 warps), fragment-packed weights,
//     merged per-timestep cell launches.
namespace {
constexpr int B_ = 16, T_ = 24, N_ = 207, D_ = 512, G_ = 1536;
constexpr int MR  = B_ * N_;        // 3312 rows per timestep
constexpr int MRP = 3328;           // padded: 26*128
constexpr int MB_ = B_ * T_ * N_;   // 79488 = 621*128

constexpr int BK = 32;              // k-chunk
constexpr int NCHUNK = D_ / BK;     // 16
constexpr int LDP = 36;             // A smem row stride: bank=(4r+qk)%32 bijective
constexpr int A_STAGE_F = 128 * LDP;   // 4608 floats (18432 B)
constexpr int B_STAGE_Q = 1024;        // 8g*4k8*32lane quads (16384 B)
constexpr int SMEM_BYTES = 2 * A_STAGE_F * 4 + 2 * B_STAGE_Q * 16;  // 69632

constexpr int CT_ = G_ / 64;        // 24 col-tiles of 64
constexpr int WQ_PER_W = CT_ * NCHUNK * B_STAGE_Q;  // 393216 quads per weight
}

// ---------------- scratch (device globals) ----------------
__device__ float g_gi0[(size_t)MB_ * G_];
__device__ float g_gh0[(size_t)MRP * G_];
__device__ float g_gi1[(size_t)MRP * G_];
__device__ float g_gh1[(size_t)MRP * G_];
__device__ float g_h0s[(size_t)MRP * D_];   // pad rows stay 0
__device__ float g_h1s[(size_t)MRP * D_];
__device__ uint4 g_Wp[4 * (size_t)WQ_PER_W];  // packed Wi0,Wi1,Wh0,Wh1

// ---------------- helpers ----------------
__device__ __forceinline__ uint32_t smem_u32(const void* p) {
    uint32_t a;
    asm("{ .reg .u64 t; cvta.to.shared.u64 t, %1; cvt.u32.u64 %0, t; }"
        : "=r"(a) : "l"(p));
    return a;
}
#define CP_ASYNC16(dst, src) \
    asm volatile("cp.async.cg.shared.global [%0], [%1], 16;" :: "r"(dst), "l"(src))
#define CP_COMMIT() asm volatile("cp.async.commit_group;" ::: "memory")
template <int N>
__device__ __forceinline__ void cp_wait() {
    asm volatile("cp.async.wait_group %0;" :: "n"(N) : "memory");
}

__device__ __forceinline__ uint32_t cvt_tf32(float x) {
    uint32_t r;
    asm("cvt.rna.tf32.f32 %0, %1;" : "=r"(r) : "f"(x));
    return r;
}
__device__ __forceinline__ void split_tf32(float x, uint32_t& hi, uint32_t& lo) {
    hi = cvt_tf32(x);
    lo = cvt_tf32(x - __uint_as_float(hi));
}

#define MMA_TF32(d, a, b0, b1)                                              \
    asm volatile("mma.sync.aligned.m16n8k8.row.col.f32.tf32.tf32.f32 "      \
        "{%0,%1,%2,%3}, {%4,%5,%6,%7}, {%8,%9}, {%0,%1,%2,%3};"             \
        : "+f"((d)[0]), "+f"((d)[1]), "+f"((d)[2]), "+f"((d)[3])            \
        : "r"((a)[0]), "r"((a)[1]), "r"((a)[2]), "r"((a)[3]),               \
          "r"(b0), "r"(b1))

// ---------------------------------------------------------------------------
// GEMM core: C tile (128x64) = A[brow..,512] @ W[bcol..]^T + bias
// A fp32 K-major; W fragment-packed (hi/lo tf32 quads). 256 thr, 8 warps:
// warpM in {0..3} (32 rows), warpN in {0,1} (32 cols).
// ---------------------------------------------------------------------------
__device__ __forceinline__ void load_stage(uint32_t sA, uint32_t sB,
                                           const float* __restrict__ Ag,
                                           const uint4* __restrict__ Bq,
                                           int ch, int tid) {
    const int k0 = ch * BK;
#pragma unroll
    for (int i = 0; i < 4; i++) {
        int s = tid + i * 256;          // 0..1023 16B slots of A
        int row = s >> 3, c4 = s & 7;
        uint32_t doff = (uint32_t)(row * LDP + c4 * 4) * 4u;
        CP_ASYNC16(sA + doff, Ag + (size_t)row * D_ + k0 + c4 * 4);
    }
    const uint4* src = Bq + (size_t)ch * B_STAGE_Q;
#pragma unroll
    for (int i = 0; i < 4; i++) {
        int s = tid + i * 256;          // 0..1023 quads of packed B
        CP_ASYNC16(sB + (uint32_t)s * 16u, src + s);
    }
}

__device__ __forceinline__ void tf32_gemm_core(const float* __restrict__ A,
                                               const uint4* __restrict__ Wp,
                                               const float* __restrict__ bias,
                                               float* __restrict__ C) {
    extern __shared__ float sm[];
    float* AsT[2] = { sm, sm + A_STAGE_F };
    uint4* BsT[2] = { (uint4*)(sm + 2 * A_STAGE_F),
                      (uint4*)(sm + 2 * A_STAGE_F) + B_STAGE_Q };

    const int tid  = threadIdx.x;
    const int lane = tid & 31, warp = tid >> 5;
    const int warpM = warp & 3, warpN = warp >> 2;
    const int r  = lane >> 2;       // 0..7
    const int qk = lane & 3;        // 0..3
    const int brow = blockIdx.y * 128;

    const float* Ag = A + (size_t)brow * D_;
    const uint4* Bq = Wp + (size_t)blockIdx.x * (NCHUNK * B_STAGE_Q);

    float acc[2][4][4];
#pragma unroll
    for (int mt = 0; mt < 2; mt++)
#pragma unroll
        for (int nt = 0; nt < 4; nt++)
#pragma unroll
            for (int i = 0; i < 4; i++) acc[mt][nt][i] = 0.f;

    load_stage(smem_u32(AsT[0]), smem_u32(BsT[0]), Ag, Bq, 0, tid);
    CP_COMMIT();
    load_stage(smem_u32(AsT[1]), smem_u32(BsT[1]), Ag, Bq, 1, tid);
    CP_COMMIT();

    for (int ch = 0; ch < NCHUNK; ch++) {
        if (ch < NCHUNK - 1) cp_wait<1>(); else cp_wait<0>();
        __syncthreads();
        const int cur = ch & 1;
        const float* as = AsT[cur] + (size_t)(warpM * 32 + r) * LDP;
        // warp's B fragments: quad index ((g*4 + k8)*32 + lane), g = warpN*4+nt
        const uint4* bw = BsT[cur] + ((size_t)warpN * 4 * 4) * 32 + lane;

#pragma unroll
        for (int k8 = 0; k8 < 4; k8++) {
            const int kk = k8 * 8 + qk;
            uint32_t ah[2][4], al[2][4];
#pragma unroll
            for (int mt = 0; mt < 2; mt++) {
                const float* p = as + mt * 16 * LDP;
                split_tf32(p[kk],                ah[mt][0], al[mt][0]);
                split_tf32(p[8 * LDP + kk],      ah[mt][1], al[mt][1]);
                split_tf32(p[kk + 4],            ah[mt][2], al[mt][2]);
                split_tf32(p[8 * LDP + kk + 4],  ah[mt][3], al[mt][3]);
            }
            uint4 bf[4];
#pragma unroll
            for (int j = 0; j < 4; j++)
                bf[j] = bw[(j * 4 + k8) * 32];
            // pass 1: al * bh
#pragma unroll
            for (int j = 0; j < 4; j++)
#pragma unroll
                for (int mt = 0; mt < 2; mt++)
                    MMA_TF32(acc[mt][j], al[mt], bf[j].x, bf[j].y);
            // pass 2: ah * bl
#pragma unroll
            for (int j = 0; j < 4; j++)
#pragma unroll
                for (int mt = 0; mt < 2; mt++)
                    MMA_TF32(acc[mt][j], ah[mt], bf[j].z, bf[j].w);
            // pass 3: ah * bh
#pragma unroll
            for (int j = 0; j < 4; j++)
#pragma unroll
                for (int mt = 0; mt < 2; mt++)
                    MMA_TF32(acc[mt][j], ah[mt], bf[j].x, bf[j].y);
        }
        __syncthreads();
        if (ch + 2 < NCHUNK) {
            load_stage(smem_u32(AsT[cur]), smem_u32(BsT[cur]), Ag, Bq, ch + 2, tid);
            CP_COMMIT();
        }
    }

    // epilogue: acc + bias -> C (float2 stores)
    const int bcol = blockIdx.x * 64;
    const int q2 = qk * 2;
#pragma unroll
    for (int mt = 0; mt < 2; mt++) {
        const int row0 = brow + warpM * 32 + mt * 16 + r;
#pragma unroll
        for (int nt = 0; nt < 4; nt++) {
            const int col = bcol + warpN * 32 + nt * 8 + q2;
            const float2 bv = *reinterpret_cast<const float2*>(bias + col);
            float2 v0 = make_float2(acc[mt][nt][0] + bv.x, acc[mt][nt][1] + bv.y);
            float2 v1 = make_float2(acc[mt][nt][2] + bv.x, acc[mt][nt][3] + bv.y);
            *reinterpret_cast<float2*>(C + (size_t)row0 * G_ + col) = v0;
            *reinterpret_cast<float2*>(C + (size_t)(row0 + 8) * G_ + col) = v1;
        }
    }
}

__global__ void __launch_bounds__(256, 3)
tf32_gemm1_kernel(const float* __restrict__ A, const uint4* __restrict__ Wp,
                  const float* __restrict__ bias, float* __restrict__ C) {
    tf32_gemm_core(A, Wp, bias, C);
}

__global__ void __launch_bounds__(256, 3)
tf32_gemm3_kernel(const float* A0, const uint4* P0, const float* b0, float* C0,
                  const float* A1, const uint4* P1, const float* b1, float* C1,
                  const float* A2, const uint4* P2, const float* b2, float* C2) {
    const float* A; const uint4* P; const float* bias; float* C;
    if (blockIdx.z == 0)      { A = A0; P = P0; bias = b0; C = C0; }
    else if (blockIdx.z == 1) { A = A1; P = P1; bias = b1; C = C1; }
    else                      { A = A2; P = P2; bias = b2; C = C2; }
    tf32_gemm_core(A, P, bias, C);
}

// ---------------------------------------------------------------------------
// Weight prepack: W[k][n] -> fragment quads [bh(k), bh(k+4), bl(k), bl(k+4)]
// layout: [z][ct64][ch][g][k8][lane] quads; block=(ct,ch,z), 256 threads.
// ---------------------------------------------------------------------------
__global__ void prepack_kernel(const float* __restrict__ Wi,
                               const float* __restrict__ Wh,
                               uint4* __restrict__ Wp) {
    __shared__ float tile[32][64];
    const int ct = blockIdx.x, ch = blockIdx.y, z = blockIdx.z;
    const float* src = (z < 2 ? Wi : Wh) + (size_t)(z & 1) * D_ * G_;
    const int tid = threadIdx.x;

    // coalesced load: 32 k-rows x 64 n-cols
#pragma unroll
    for (int i = 0; i < 8; i++) {
        int s = tid + i * 256;          // 0..2047
        int kk = s >> 6, n = s & 63;
        tile[kk][n] = src[(size_t)(ch * 32 + kk) * G_ + ct * 64 + n];
    }
    __syncthreads();

    uint4* dst = Wp + ((size_t)z * CT_ * NCHUNK + (size_t)ct * NCHUNK + ch) * B_STAGE_Q;
#pragma unroll
    for (int i = 0; i < 4; i++) {
        int e = tid + i * 256;          // 0..1023
        int g = e >> 7, k8 = (e >> 5) & 3, ln = e & 31;
        int rr = ln >> 2, qq = ln & 3;
        int nl = g * 8 + rr;            // 0..63
        int kl = k8 * 8 + qq;
        uint32_t h0, l0, h1, l1;
        split_tf32(tile[kl][nl],     h0, l0);
        split_tf32(tile[kl + 4][nl], h1, l1);
        uint4 q; q.x = h0; q.y = h1; q.z = l0; q.w = l1;
        dst[e] = q;
    }
}

// ---------------------------------------------------------------------------
// Fused GRU cell + LayerNorm (128 thr x float4 = 512 = D)
// ---------------------------------------------------------------------------
__device__ __forceinline__ float sigf(float v) { return 1.f / (1.f + expf(-v)); }

__device__ __forceinline__ void cell_body(const float* __restrict__ gi,
                                          const float* __restrict__ ghrow,
                                          float* __restrict__ hrow,
                                          const float* __restrict__ gamma,
                                          const float* __restrict__ beta,
                                          float* __restrict__ o2) {
    const float4* gi4 = reinterpret_cast<const float4*>(gi);
    const float4* gh4 = reinterpret_cast<const float4*>(ghrow);
    float4* h4 = reinterpret_cast<float4*>(hrow);
    int tid = threadIdx.x;

    float4 ir = gi4[tid], iz = gi4[128 + tid], inn = gi4[256 + tid];
    float4 hr = gh4[tid], hz = gh4[128 + tid], hn = gh4[256 + tid];
    float4 hv = h4[tid];

    float o[4];
    {
        float rr, z, nv;
        rr = sigf(ir.x + hr.x); z = sigf(iz.x + hz.x); nv = tanhf(inn.x + rr * hn.x);
        o[0] = nv + z * (hv.x - nv);
        rr = sigf(ir.y + hr.y); z = sigf(iz.y + hz.y); nv = tanhf(inn.y + rr * hn.y);
        o[1] = nv + z * (hv.y - nv);
        rr = sigf(ir.z + hr.z); z = sigf(iz.z + hz.z); nv = tanhf(inn.z + rr * hn.z);
        o[2] = nv + z * (hv.z - nv);
        rr = sigf(ir.w + hr.w); z = sigf(iz.w + hz.w); nv = tanhf(inn.w + rr * hn.w);
        o[3] = nv + z * (hv.w - nv);
    }
    float s = o[0] + o[1] + o[2] + o[3];
    float s2 = o[0]*o[0] + o[1]*o[1] + o[2]*o[2] + o[3]*o[3];
#pragma unroll
    for (int off = 16; off > 0; off >>= 1) {
        s  += __shfl_xor_sync(0xffffffffu, s,  off);
        s2 += __shfl_xor_sync(0xffffffffu, s2, off);
    }
    __shared__ float sh[4], sh2[4];
    int w = tid >> 5;
    if ((tid & 31) == 0) { sh[w] = s; sh2[w] = s2; }
    __syncthreads();
    s  = sh[0]  + sh[1]  + sh[2]  + sh[3];
    s2 = sh2[0] + sh2[1] + sh2[2] + sh2[3];
    float mu  = s * (1.f / D_);
    float var = s2 * (1.f / D_) - mu * mu;
    float inv = rsqrtf(var + 1e-5f);

    const float4 g4 = reinterpret_cast<const float4*>(gamma)[tid];
    const float4 b4 = reinterpret_cast<const float4*>(beta)[tid];
    float4 y;
    y.x = (o[0] - mu) * inv * g4.x + b4.x;
    y.y = (o[1] - mu) * inv * g4.y + b4.y;
    y.z = (o[2] - mu) * inv * g4.z + b4.z;
    y.w = (o[3] - mu) * inv * g4.w + b4.w;
    h4[tid] = y;
    if (o2) reinterpret_cast<float4*>(o2)[tid] = y;
}

// single cell (used once for cell0(0))
__global__ void __launch_bounds__(128)
gru_cell(const float* __restrict__ gi_base, int t,
         const float* __restrict__ gh, float* __restrict__ h,
         const float* __restrict__ gamma, const float* __restrict__ beta) {
    int m = blockIdx.x;
    int b = m / N_, n = m % N_;
    const float* gi = gi_base + ((size_t)(b * T_ + t) * N_ + n) * G_;
    cell_body(gi, gh + (size_t)m * G_, h + (size_t)m * D_, gamma, beta, nullptr);
}

// merged per-timestep cells: z=0 -> cell1(t) (writes out), z=1 -> cell0(t+1)
__global__ void __launch_bounds__(128)
gru_cell2(const float* __restrict__ gi0_base, const float* __restrict__ gi1,
          int tnext,
          const float* __restrict__ gh0, const float* __restrict__ gh1,
          float* __restrict__ h0s, float* __restrict__ h1s,
          const float* __restrict__ gamma, const float* __restrict__ beta,
          float* __restrict__ out, int t_out) {
    int m = blockIdx.x;
    int b = m / N_, n = m % N_;
    if (blockIdx.z == 0) {
        float* o2 = out + ((size_t)(b * T_ + t_out) * N_ + n) * D_;
        cell_body(gi1 + (size_t)m * G_, gh1 + (size_t)m * G_,
                  h1s + (size_t)m * D_, gamma + D_, beta + D_, o2);
    } else {
        const float* gi = gi0_base + ((size_t)(b * T_ + tnext) * N_ + n) * G_;
        cell_body(gi, gh0 + (size_t)m * G_, h0s + (size_t)m * D_,
                  gamma, beta, nullptr);
    }
}

// ---------------------------------------------------------------------------
__global__ void init_h_kernel(const float* __restrict__ h0,
                              float* __restrict__ h0s, float* __restrict__ h1s) {
    int i = blockIdx.x * blockDim.x + threadIdx.x;
    if (i >= 2 * MR * D_) return;
    int d = i % D_;
    int r = i / D_;
    int n = r % N_; r /= N_;
    int l = r % 2;
    int b = r / 2;
    float v = h0[i];
    float* dst = (l == 0) ? h0s : h1s;
    dst[((size_t)b * N_ + n) * D_ + d] = v;
}

__global__ void write_hidden_kernel(const float* __restrict__ h0s,
                                    const float* __restrict__ h1s,
                                    float* __restrict__ dst) {
    int i = blockIdx.x * blockDim.x + threadIdx.x;
    if (i >= 2 * MR * D_) return;
    int d = i % D_;
    int r = i / D_;
    int n = r % N_; r /= N_;
    int l = r % 2;
    int b = r / 2;
    const float* src = (l == 0) ? h0s : h1s;
    dst[i] = src[((size_t)b * N_ + n) * D_ + d];
}

// ---------------------------------------------------------------------------
extern "C" void kernel_launch(void* const* d_in, const int* in_sizes, int n_in,
                              void* d_out, int out_size) {
    (void)in_sizes; (void)n_in;
    const float* x     = (const float*)d_in[0];
    const float* h0    = (const float*)d_in[1];
    const float* Wi    = (const float*)d_in[2];
    const float* bi    = (const float*)d_in[3];
    const float* Wh    = (const float*)d_in[4];
    const float* bh    = (const float*)d_in[5];
    const float* gamma = (const float*)d_in[6];
    const float* beta  = (const float*)d_in[7];
    float* out = (float*)d_out;

    float *gi0, *gh0, *gi1, *gh1, *h0s, *h1s;
    uint4* Wp;
    cudaGetSymbolAddress((void**)&gi0, g_gi0);
    cudaGetSymbolAddress((void**)&gh0, g_gh0);
    cudaGetSymbolAddress((void**)&gi1, g_gi1);
    cudaGetSymbolAddress((void**)&gh1, g_gh1);
    cudaGetSymbolAddress((void**)&h0s, g_h0s);
    cudaGetSymbolAddress((void**)&h1s, g_h1s);
    cudaGetSymbolAddress((void**)&Wp,  g_Wp);

    cudaFuncSetAttribute(tf32_gemm1_kernel,
                         cudaFuncAttributeMaxDynamicSharedMemorySize, SMEM_BYTES);
    cudaFuncSetAttribute(tf32_gemm3_kernel,
                         cudaFuncAttributeMaxDynamicSharedMemorySize, SMEM_BYTES);

    const uint4* Wi0p = Wp;
    const uint4* Wi1p = Wp + (size_t)WQ_PER_W;
    const uint4* Wh0p = Wp + (size_t)2 * WQ_PER_W;
    const uint4* Wh1p = Wp + (size_t)3 * WQ_PER_W;

    prepack_kernel<<<dim3(CT_, NCHUNK, 4), 256>>>(Wi, Wh, Wp);
    {
        int tot = 2 * MR * D_;
        init_h_kernel<<<(tot + 255) / 256, 256>>>(h0, h0s, h1s);
    }

    // Hoisted layer-0 input GEMM (all timesteps): gi0 = x @ Wi0 + bi0
    tf32_gemm1_kernel<<<dim3(CT_, MB_ / 128), 256, SMEM_BYTES>>>(x, Wi0p, bi, gi0);

    // GH0(0) = h0 @ Wh0 + bh0, then cell0(0)
    tf32_gemm1_kernel<<<dim3(CT_, MRP / 128), 256, SMEM_BYTES>>>(h0s, Wh0p, bh, gh0);
    gru_cell<<<MR, 128>>>(gi0, 0, gh0, h0s, gamma, beta);

    for (int t = 0; t < T_; t++) {
        int nz_g = (t == T_ - 1) ? 2 : 3;
        // z=0: GI1(t)=out0(t)@Wi1 ; z=1: GH1(t)=h1@Wh1 ; z=2: GH0(t+1)=out0(t)@Wh0
        tf32_gemm3_kernel<<<dim3(CT_, MRP / 128, nz_g), 256, SMEM_BYTES>>>(
            h0s, Wi1p, bi + G_, gi1,
            h1s, Wh1p, bh + G_, gh1,
            h0s, Wh0p, bh,      gh0);
        int nz_c = (t == T_ - 1) ? 1 : 2;
        gru_cell2<<<dim3(MR, 1, nz_c), 128>>>(gi0, gi1, t + 1, gh0, gh1,
                                              h0s, h1s, gamma, beta, out, t);
    }

    long long need = (long long)MB_ * D_ + (long long)2 * MR * D_;
    if ((long long)out_size >= need) {
        int tot = 2 * MR * D_;
        write_hidden_kernel<<<(tot + 255) / 256, 256>>>(h0s, h1s,
                                                        out + (size_t)MB_ * D_);
    }
}

// round 7
// speedup vs baseline: 1.1208x; 1.1208x over previous
#include <cuda_runtime.h>
#include <math.h>
#include <stdint.h>

// GraphRNN: 2-layer LayerNorm-GRU scan. B=16, T=24, N=207, D=512, G=1536.
// R7: all GEMM operands pre-split to tf32 hi/lo fragment-packed form by the
//     producing kernels; GEMM mainloop = pure LDS.128 + HMMA; 128x128 tiles,
//     BK=16, 3-stage cp.async pipeline, 1 sync/iter.
namespace {
constexpr int B_ = 16, T_ = 24, N_ = 207, D_ = 512, G_ = 1536;
constexpr int MR  = B_ * N_;        // 3312 rows per timestep
constexpr int MRP = 3328;           // padded: 26*128
constexpr int MB_ = B_ * T_ * N_;   // 79488 = 621*128

constexpr int BK = 16;              // k-chunk
constexpr int NCHUNK = D_ / BK;     // 32
constexpr int CT_ = G_ / 128;       // 12 col-tiles
constexpr int RT_R = MRP / 128;     // 26 recurrent row-tiles
constexpr int RT_X = MB_ / 128;     // 621 row-tiles for x

// per (rowtile, chunk): A packed = 1024 quads (512 hi then 512 lo) = 16KB
// per (coltile, chunk): B packed = 1024 quads = 16KB
constexpr int STAGE_Q = 2048;       // A(1024) + B(1024) quads per stage
constexpr int STAGES = 3;
constexpr int SMEM_BYTES = STAGES * STAGE_Q * 16;  // 98304

constexpr size_t WQ_PER_W = (size_t)CT_ * NCHUNK * 1024;   // 393216
constexpr size_t HQ = (size_t)RT_R * NCHUNK * 1024;        // 851968
constexpr size_t XQ = (size_t)RT_X * NCHUNK * 1024;        // 20348928
}

// ---------------- scratch (device globals; zero-initialized) ----------------
__device__ float g_gi0[(size_t)MB_ * G_];
__device__ float g_gh0[(size_t)MRP * G_];
__device__ float g_gi1[(size_t)MRP * G_];
__device__ float g_gh1[(size_t)MRP * G_];
__device__ float g_h0s[(size_t)MRP * D_];   // fp32 state (pad rows stay 0)
__device__ float g_h1s[(size_t)MRP * D_];
__device__ uint4 g_h0p[HQ];                 // packed state (pads stay 0)
__device__ uint4 g_h1p[HQ];
__device__ uint4 g_xp[XQ];                  // packed x
__device__ uint4 g_Wp[4 * WQ_PER_W];        // packed Wi0,Wi1,Wh0,Wh1

// ---------------- helpers ----------------
__device__ __forceinline__ uint32_t smem_u32(const void* p) {
    uint32_t a;
    asm("{ .reg .u64 t; cvta.to.shared.u64 t, %1; cvt.u32.u64 %0, t; }"
        : "=r"(a) : "l"(p));
    return a;
}
#define CP_ASYNC16(dst, src) \
    asm volatile("cp.async.cg.shared.global [%0], [%1], 16;" :: "r"(dst), "l"(src))
#define CP_COMMIT() asm volatile("cp.async.commit_group;" ::: "memory")
template <int N>
__device__ __forceinline__ void cp_wait() {
    asm volatile("cp.async.wait_group %0;" :: "n"(N) : "memory");
}

__device__ __forceinline__ uint32_t cvt_tf32(float x) {
    uint32_t r;
    asm("cvt.rna.tf32.f32 %0, %1;" : "=r"(r) : "f"(x));
    return r;
}
__device__ __forceinline__ void split_tf32(float x, uint32_t& hi, uint32_t& lo) {
    hi = cvt_tf32(x);
    lo = cvt_tf32(x - __uint_as_float(hi));
}

#define MMA_TF32(d, a, b0, b1)                                              \
    asm volatile("mma.sync.aligned.m16n8k8.row.col.f32.tf32.tf32.f32 "      \
        "{%0,%1,%2,%3}, {%4,%5,%6,%7}, {%8,%9}, {%0,%1,%2,%3};"             \
        : "+f"((d)[0]), "+f"((d)[1]), "+f"((d)[2]), "+f"((d)[3])            \
        : "r"((a)[0]), "r"((a)[1]), "r"((a)[2]), "r"((a)[3]),               \
          "r"(b0), "r"(b1))

// ---------------------------------------------------------------------------
// Packed-activation writer: element (row m, col d) with hi/lo words.
// Layout per (rowtile rt, chunk ch): 1024 quads = [hi: (mg*2+k8)*32+lane][512..lo]
// quad components s: 0:(r,kk) 1:(r+8,kk) 2:(r,kk+4) 3:(r+8,kk+4)
// ---------------------------------------------------------------------------
__device__ __forceinline__ void write_packed4(uint32_t* Ap, int m, int d0,
                                              const uint32_t* hi,
                                              const uint32_t* lo) {
    int rt = m >> 7, mrow = m & 127;
    int mg = mrow >> 4, rr = mrow & 15;
    int ch = d0 >> 4, kd = d0 & 15;
    int k8 = kd >> 3, chalf = (kd & 7) >> 2;
    int s = (rr >> 3) + chalf * 2;
    int lane0 = (rr & 7) * 4;
    size_t qhi = ((size_t)rt * NCHUNK + ch) * 1024 + (mg * 2 + k8) * 32 + lane0;
#pragma unroll
    for (int j = 0; j < 4; j++) {
        Ap[(qhi + j) * 4 + s]       = hi[j];
        Ap[(qhi + 512 + j) * 4 + s] = lo[j];
    }
}

// ---------------------------------------------------------------------------
// GEMM core: C tile (128x128) = A[rt] @ W[ct]^T + bias. 256 thr, 8 warps
// (warpM 0..3 x warpN 0..1). Pure LDS.128 + HMMA mainloop.
// ---------------------------------------------------------------------------
__device__ __forceinline__ void load_stage(uint32_t sS, const uint4* __restrict__ Aq,
                                           const uint4* __restrict__ Bq,
                                           int ch, int tid) {
    const uint4* a = Aq + (size_t)ch * 1024;
    const uint4* b = Bq + (size_t)ch * 1024;
#pragma unroll
    for (int i = 0; i < 4; i++) {
        int s = tid + i * 256;
        CP_ASYNC16(sS + (uint32_t)s * 16u, a + s);
    }
#pragma unroll
    for (int i = 0; i < 4; i++) {
        int s = tid + i * 256;
        CP_ASYNC16(sS + 16384u + (uint32_t)s * 16u, b + s);
    }
}

__device__ __forceinline__ void tf32_gemm_core(const uint4* __restrict__ Ap,
                                               const uint4* __restrict__ Wp,
                                               const float* __restrict__ bias,
                                               float* __restrict__ C) {
    extern __shared__ uint4 smq[];

    const int tid  = threadIdx.x;
    const int lane = tid & 31, warp = tid >> 5;
    const int warpM = warp & 3, warpN = warp >> 2;
    const int r  = lane >> 2;
    const int qk = lane & 3;

    const uint4* Aq = Ap + (size_t)blockIdx.y * (NCHUNK * 1024);
    const uint4* Bq = Wp + (size_t)blockIdx.x * (NCHUNK * 1024);

    float acc[2][8][4];
#pragma unroll
    for (int mt = 0; mt < 2; mt++)
#pragma unroll
        for (int nt = 0; nt < 8; nt++)
#pragma unroll
            for (int i = 0; i < 4; i++) acc[mt][nt][i] = 0.f;

    uint32_t sb = smem_u32(smq);
    load_stage(sb, Aq, Bq, 0, tid);
    CP_COMMIT();
    load_stage(sb + STAGE_Q * 16, Aq, Bq, 1, tid);
    CP_COMMIT();

    for (int ch = 0; ch < NCHUNK; ch++) {
        if (ch < NCHUNK - 1) cp_wait<1>(); else cp_wait<0>();
        __syncthreads();
        if (ch + 2 < NCHUNK) {
            load_stage(sb + ((ch + 2) % STAGES) * (STAGE_Q * 16), Aq, Bq, ch + 2, tid);
            CP_COMMIT();
        }
        const uint4* As = smq + (size_t)(ch % STAGES) * STAGE_Q;
        const uint4* Bs = As + 1024;

#pragma unroll
        for (int k8 = 0; k8 < 2; k8++) {
            uint4 ah[2], al[2];
#pragma unroll
            for (int mt = 0; mt < 2; mt++) {
                int mg = warpM * 2 + mt;
                int ai = (mg * 2 + k8) * 32 + lane;
                ah[mt] = As[ai];
                al[mt] = As[ai + 512];
            }
#pragma unroll
            for (int half = 0; half < 2; half++) {
                uint4 bf[4];
#pragma unroll
                for (int j = 0; j < 4; j++) {
                    int g = warpN * 8 + half * 4 + j;
                    bf[j] = Bs[(g * 2 + k8) * 32 + lane];
                }
                // pass 1: al * bh
#pragma unroll
                for (int j = 0; j < 4; j++)
#pragma unroll
                    for (int mt = 0; mt < 2; mt++)
                        MMA_TF32(acc[mt][half * 4 + j],
                                 ((const uint32_t*)&al[mt]), bf[j].x, bf[j].y);
                // pass 2: ah * bl
#pragma unroll
                for (int j = 0; j < 4; j++)
#pragma unroll
                    for (int mt = 0; mt < 2; mt++)
                        MMA_TF32(acc[mt][half * 4 + j],
                                 ((const uint32_t*)&ah[mt]), bf[j].z, bf[j].w);
                // pass 3: ah * bh
#pragma unroll
                for (int j = 0; j < 4; j++)
#pragma unroll
                    for (int mt = 0; mt < 2; mt++)
                        MMA_TF32(acc[mt][half * 4 + j],
                                 ((const uint32_t*)&ah[mt]), bf[j].x, bf[j].y);
            }
        }
    }

    // epilogue: acc + bias -> C (float2 stores)
    const int brow = blockIdx.y * 128;
    const int bcol = blockIdx.x * 128;
    const int q2 = qk * 2;
#pragma unroll
    for (int mt = 0; mt < 2; mt++) {
        const int row0 = brow + warpM * 32 + mt * 16 + r;
#pragma unroll
        for (int nt = 0; nt < 8; nt++) {
            const int col = bcol + warpN * 64 + nt * 8 + q2;
            const float2 bv = *reinterpret_cast<const float2*>(bias + col);
            float2 v0 = make_float2(acc[mt][nt][0] + bv.x, acc[mt][nt][1] + bv.y);
            float2 v1 = make_float2(acc[mt][nt][2] + bv.x, acc[mt][nt][3] + bv.y);
            *reinterpret_cast<float2*>(C + (size_t)row0 * G_ + col) = v0;
            *reinterpret_cast<float2*>(C + (size_t)(row0 + 8) * G_ + col) = v1;
        }
    }
}

__global__ void __launch_bounds__(256, 2)
tf32_gemm1_kernel(const uint4* __restrict__ Ap, const uint4* __restrict__ Wp,
                  const float* __restrict__ bias, float* __restrict__ C) {
    tf32_gemm_core(Ap, Wp, bias, C);
}

__global__ void __launch_bounds__(256, 2)
tf32_gemm3_kernel(const uint4* A0, const uint4* P0, const float* b0, float* C0,
                  const uint4* A1, const uint4* P1, const float* b1, float* C1,
                  const uint4* A2, const uint4* P2, const float* b2, float* C2) {
    const uint4* A; const uint4* P; const float* bias; float* C;
    if (blockIdx.z == 0)      { A = A0; P = P0; bias = b0; C = C0; }
    else if (blockIdx.z == 1) { A = A1; P = P1; bias = b1; C = C1; }
    else                      { A = A2; P = P2; bias = b2; C = C2; }
    tf32_gemm_core(A, P, bias, C);
}

// ---------------------------------------------------------------------------
// Weight prepack (BK=16): quad e=(g*2+k8)*32+lane holds
// [bh(kk),bh(kk+4),bl(kk),bl(kk+4)] for col g*8+(lane>>2), kk=k8*8+(lane&3).
// ---------------------------------------------------------------------------
__global__ void prepack_kernel(const float* __restrict__ Wi,
                               const float* __restrict__ Wh,
                               uint4* __restrict__ Wp) {
    __shared__ float tile[16][128];
    const int ct = blockIdx.x, ch = blockIdx.y, z = blockIdx.z;
    const float* src = (z < 2 ? Wi : Wh) + (size_t)(z & 1) * D_ * G_;
    const int tid = threadIdx.x;

#pragma unroll
    for (int i = 0; i < 8; i++) {
        int s = tid + i * 256;          // 0..2047
        int kk = s >> 7, n = s & 127;
        tile[kk][n] = src[(size_t)(ch * BK + kk) * G_ + ct * 128 + n];
    }
    __syncthreads();

    uint4* dst = Wp + ((size_t)z * CT_ + ct) * (NCHUNK * 1024) + (size_t)ch * 1024;
#pragma unroll
    for (int i = 0; i < 4; i++) {
        int e = tid + i * 256;          // 0..1023
        int lane = e & 31, k8 = (e >> 5) & 1, g = e >> 6;
        int rr = lane >> 2, qq = lane & 3;
        int nl = g * 8 + rr;
        int kl = k8 * 8 + qq;
        uint32_t h0, l0, h1, l1;
        split_tf32(tile[kl][nl],     h0, l0);
        split_tf32(tile[kl + 4][nl], h1, l1);
        uint4 q; q.x = h0; q.y = h1; q.z = l0; q.w = l1;
        dst[e] = q;
    }
}

// ---------------------------------------------------------------------------
// x prepack: one block per row of x, packed into g_xp.
// ---------------------------------------------------------------------------
__global__ void xpack_kernel(const float* __restrict__ x, uint4* __restrict__ xp) {
    int m = blockIdx.x;
    int tid = threadIdx.x;
    float4 v = reinterpret_cast<const float4*>(x + (size_t)m * D_)[tid];
    uint32_t hi[4], lo[4];
    split_tf32(v.x, hi[0], lo[0]);
    split_tf32(v.y, hi[1], lo[1]);
    split_tf32(v.z, hi[2], lo[2]);
    split_tf32(v.w, hi[3], lo[3]);
    write_packed4((uint32_t*)xp, m, tid * 4, hi, lo);
}

// ---------------------------------------------------------------------------
// Fused GRU cell + LayerNorm (128 thr x float4 = 512 = D); writes fp32 state,
// packed state, and optionally the output tensor.
// ---------------------------------------------------------------------------
__device__ __forceinline__ float sigf(float v) { return 1.f / (1.f + expf(-v)); }

__device__ __forceinline__ void cell_body(const float* __restrict__ gi,
                                          const float* __restrict__ ghrow,
                                          float* __restrict__ hrow,
                                          uint32_t* __restrict__ hpack, int m,
                                          const float* __restrict__ gamma,
                                          const float* __restrict__ beta,
                                          float* __restrict__ o2) {
    const float4* gi4 = reinterpret_cast<const float4*>(gi);
    const float4* gh4 = reinterpret_cast<const float4*>(ghrow);
    float4* h4 = reinterpret_cast<float4*>(hrow);
    int tid = threadIdx.x;

    float4 ir = gi4[tid], iz = gi4[128 + tid], inn = gi4[256 + tid];
    float4 hr = gh4[tid], hz = gh4[128 + tid], hn = gh4[256 + tid];
    float4 hv = h4[tid];

    float o[4];
    {
        float rr, z, nv;
        rr = sigf(ir.x + hr.x); z = sigf(iz.x + hz.x); nv = tanhf(inn.x + rr * hn.x);
        o[0] = nv + z * (hv.x - nv);
        rr = sigf(ir.y + hr.y); z = sigf(iz.y + hz.y); nv = tanhf(inn.y + rr * hn.y);
        o[1] = nv + z * (hv.y - nv);
        rr = sigf(ir.z + hr.z); z = sigf(iz.z + hz.z); nv = tanhf(inn.z + rr * hn.z);
        o[2] = nv + z * (hv.z - nv);
        rr = sigf(ir.w + hr.w); z = sigf(iz.w + hz.w); nv = tanhf(inn.w + rr * hn.w);
        o[3] = nv + z * (hv.w - nv);
    }
    float s = o[0] + o[1] + o[2] + o[3];
    float s2 = o[0]*o[0] + o[1]*o[1] + o[2]*o[2] + o[3]*o[3];
#pragma unroll
    for (int off = 16; off > 0; off >>= 1) {
        s  += __shfl_xor_sync(0xffffffffu, s,  off);
        s2 += __shfl_xor_sync(0xffffffffu, s2, off);
    }
    __shared__ float sh[4], sh2[4];
    int w = tid >> 5;
    if ((tid & 31) == 0) { sh[w] = s; sh2[w] = s2; }
    __syncthreads();
    s  = sh[0]  + sh[1]  + sh[2]  + sh[3];
    s2 = sh2[0] + sh2[1] + sh2[2] + sh2[3];
    float mu  = s * (1.f / D_);
    float var = s2 * (1.f / D_) - mu * mu;
    float inv = rsqrtf(var + 1e-5f);

    const float4 g4 = reinterpret_cast<const float4*>(gamma)[tid];
    const float4 b4 = reinterpret_cast<const float4*>(beta)[tid];
    float y[4];
    y[0] = (o[0] - mu) * inv * g4.x + b4.x;
    y[1] = (o[1] - mu) * inv * g4.y + b4.y;
    y[2] = (o[2] - mu) * inv * g4.z + b4.z;
    y[3] = (o[3] - mu) * inv * g4.w + b4.w;
    h4[tid] = make_float4(y[0], y[1], y[2], y[3]);
    uint32_t hi[4], lo[4];
#pragma unroll
    for (int j = 0; j < 4; j++) split_tf32(y[j], hi[j], lo[j]);
    write_packed4(hpack, m, tid * 4, hi, lo);
    if (o2) reinterpret_cast<float4*>(o2)[tid] =
        make_float4(y[0], y[1], y[2], y[3]);
}

// single cell (cell0 at t=0)
__global__ void __launch_bounds__(128)
gru_cell(const float* __restrict__ gi_base, int t,
         const float* __restrict__ gh, float* __restrict__ h,
         uint32_t* __restrict__ hpack,
         const float* __restrict__ gamma, const float* __restrict__ beta) {
    int m = blockIdx.x;
    int b = m / N_, n = m % N_;
    const float* gi = gi_base + ((size_t)(b * T_ + t) * N_ + n) * G_;
    cell_body(gi, gh + (size_t)m * G_, h + (size_t)m * D_, hpack, m,
              gamma, beta, nullptr);
}

// merged per-timestep cells: z=0 -> cell1(t) (writes out), z=1 -> cell0(t+1)
__global__ void __launch_bounds__(128)
gru_cell2(const float* __restrict__ gi0_base, const float* __restrict__ gi1,
          int tnext,
          const float* __restrict__ gh0, const float* __restrict__ gh1,
          float* __restrict__ h0s, float* __restrict__ h1s,
          uint32_t* __restrict__ h0p, uint32_t* __restrict__ h1p,
          const float* __restrict__ gamma, const float* __restrict__ beta,
          float* __restrict__ out, int t_out) {
    int m = blockIdx.x;
    int b = m / N_, n = m % N_;
    if (blockIdx.z == 0) {
        float* o2 = out + ((size_t)(b * T_ + t_out) * N_ + n) * D_;
        cell_body(gi1 + (size_t)m * G_, gh1 + (size_t)m * G_,
                  h1s + (size_t)m * D_, h1p, m, gamma + D_, beta + D_, o2);
    } else {
        const float* gi = gi0_base + ((size_t)(b * T_ + tnext) * N_ + n) * G_;
        cell_body(gi, gh0 + (size_t)m * G_, h0s + (size_t)m * D_, h0p, m,
                  gamma, beta, nullptr);
    }
}

// ---------------------------------------------------------------------------
__global__ void init_h_kernel(const float* __restrict__ h0,
                              float* __restrict__ h0s, float* __restrict__ h1s,
                              uint32_t* __restrict__ h0p,
                              uint32_t* __restrict__ h1p) {
    // one block per (b, l, n) row: 16*2*207 = 6624 blocks, 128 threads
    int row = blockIdx.x;
    int n = row % N_;
    int l = (row / N_) % 2;
    int b = row / (2 * N_);
    int tid = threadIdx.x;
    int m = b * N_ + n;
    float4 v = reinterpret_cast<const float4*>(h0 + (size_t)row * D_)[tid];
    float* hs = (l == 0) ? h0s : h1s;
    reinterpret_cast<float4*>(hs + (size_t)m * D_)[tid] = v;
    uint32_t hi[4], lo[4];
    split_tf32(v.x, hi[0], lo[0]);
    split_tf32(v.y, hi[1], lo[1]);
    split_tf32(v.z, hi[2], lo[2]);
    split_tf32(v.w, hi[3], lo[3]);
    write_packed4((l == 0) ? h0p : h1p, m, tid * 4, hi, lo);
}

__global__ void write_hidden_kernel(const float* __restrict__ h0s,
                                    const float* __restrict__ h1s,
                                    float* __restrict__ dst) {
    int i = blockIdx.x * blockDim.x + threadIdx.x;
    if (i >= 2 * MR * D_) return;
    int d = i % D_;
    int r = i / D_;
    int n = r % N_; r /= N_;
    int l = r % 2;
    int b = r / 2;
    const float* src = (l == 0) ? h0s : h1s;
    dst[i] = src[((size_t)b * N_ + n) * D_ + d];
}

// ---------------------------------------------------------------------------
extern "C" void kernel_launch(void* const* d_in, const int* in_sizes, int n_in,
                              void* d_out, int out_size) {
    (void)in_sizes; (void)n_in;
    const float* x     = (const float*)d_in[0];
    const float* h0    = (const float*)d_in[1];
    const float* Wi    = (const float*)d_in[2];
    const float* bi    = (const float*)d_in[3];
    const float* Wh    = (const float*)d_in[4];
    const float* bh    = (const float*)d_in[5];
    const float* gamma = (const float*)d_in[6];
    const float* beta  = (const float*)d_in[7];
    float* out = (float*)d_out;

    float *gi0, *gh0, *gi1, *gh1, *h0s, *h1s;
    uint4 *h0p, *h1p, *xp, *Wp;
    cudaGetSymbolAddress((void**)&gi0, g_gi0);
    cudaGetSymbolAddress((void**)&gh0, g_gh0);
    cudaGetSymbolAddress((void**)&gi1, g_gi1);
    cudaGetSymbolAddress((void**)&gh1, g_gh1);
    cudaGetSymbolAddress((void**)&h0s, g_h0s);
    cudaGetSymbolAddress((void**)&h1s, g_h1s);
    cudaGetSymbolAddress((void**)&h0p, g_h0p);
    cudaGetSymbolAddress((void**)&h1p, g_h1p);
    cudaGetSymbolAddress((void**)&xp,  g_xp);
    cudaGetSymbolAddress((void**)&Wp,  g_Wp);

    cudaFuncSetAttribute(tf32_gemm1_kernel,
                         cudaFuncAttributeMaxDynamicSharedMemorySize, SMEM_BYTES);
    cudaFuncSetAttribute(tf32_gemm3_kernel,
                         cudaFuncAttributeMaxDynamicSharedMemorySize, SMEM_BYTES);

    const uint4* Wi0p = Wp;
    const uint4* Wi1p = Wp + WQ_PER_W;
    const uint4* Wh0p = Wp + 2 * WQ_PER_W;
    const uint4* Wh1p = Wp + 3 * WQ_PER_W;

    prepack_kernel<<<dim3(CT_, NCHUNK, 4), 256>>>(Wi, Wh, Wp);
    init_h_kernel<<<2 * MR, 128>>>(h0, h0s, h1s, (uint32_t*)h0p, (uint32_t*)h1p);
    xpack_kernel<<<MB_, 128>>>(x, xp);

    // Hoisted layer-0 input GEMM (all timesteps): gi0 = x @ Wi0 + bi0
    tf32_gemm1_kernel<<<dim3(CT_, RT_X), 256, SMEM_BYTES>>>(xp, Wi0p, bi, gi0);

    // GH0(0) = h0 @ Wh0 + bh0, then cell0(0)
    tf32_gemm1_kernel<<<dim3(CT_, RT_R), 256, SMEM_BYTES>>>(h0p, Wh0p, bh, gh0);
    gru_cell<<<MR, 128>>>(gi0, 0, gh0, h0s, (uint32_t*)h0p, gamma, beta);

    for (int t = 0; t < T_; t++) {
        int nz_g = (t == T_ - 1) ? 2 : 3;
        // z=0: GI1(t)=out0(t)@Wi1 ; z=1: GH1(t)=h1@Wh1 ; z=2: GH0(t+1)=out0(t)@Wh0
        tf32_gemm3_kernel<<<dim3(CT_, RT_R, nz_g), 256, SMEM_BYTES>>>(
            h0p, Wi1p, bi + G_, gi1,
            h1p, Wh1p, bh + G_, gh1,
            h0p, Wh0p, bh,      gh0);
        int nz_c = (t == T_ - 1) ? 1 : 2;
        gru_cell2<<<dim3(MR, 1, nz_c), 128>>>(gi0, gi1, t + 1, gh0, gh1,
                                              h0s, h1s,
                                              (uint32_t*)h0p, (uint32_t*)h1p,
                                              gamma, beta, out, t);
    }

    long long need = (long long)MB_ * D_ + (long long)2 * MR * D_;
    if ((long long)out_size >= need) {
        int tot = 2 * MR * D_;
        write_hidden_kernel<<<(tot + 255) / 256, 256>>>(h0s, h1s,
                                                        out + (size_t)MB_ * D_);
    }
}

// round 8
// speedup vs baseline: 1.1724x; 1.0461x over previous
#include <cuda_runtime.h>
#include <math.h>
#include <stdint.h>

// GraphRNN: 2-layer LayerNorm-GRU scan. B=16, T=24, N=207, D=512, G=1536.
// R8: pre-split tf32 hi/lo fragment-packed operands (pure LDS+HMMA mainloop),
//     128x64 tiles @ 3 CTAs/SM, BK=16, 3-stage cp.async pipeline.
namespace {
constexpr int B_ = 16, T_ = 24, N_ = 207, D_ = 512, G_ = 1536;
constexpr int MR  = B_ * N_;        // 3312 rows per timestep
constexpr int MRP = 3328;           // padded: 26*128
constexpr int MB_ = B_ * T_ * N_;   // 79488 = 621*128

constexpr int BK = 16;              // k-chunk
constexpr int NCHUNK = D_ / BK;     // 32
constexpr int CT_ = G_ / 64;        // 24 col-tiles of 64
constexpr int RT_R = MRP / 128;     // 26 recurrent row-tiles
constexpr int RT_X = MB_ / 128;     // 621 row-tiles for x

// per (rowtile, chunk): A packed = 1024 quads (512 hi + 512 lo) = 16KB
// per (coltile64, chunk): B packed = 512 quads = 8KB
constexpr int A_Q = 1024, B_Q = 512;
constexpr int STAGE_Q = A_Q + B_Q;  // 1536 quads = 24KB
constexpr int STAGES = 3;
constexpr int SMEM_BYTES = STAGES * STAGE_Q * 16;  // 73728

constexpr size_t WQ_PER_W = (size_t)CT_ * NCHUNK * B_Q;   // 393216
constexpr size_t HQ = (size_t)RT_R * NCHUNK * A_Q;        // 851968
constexpr size_t XQ = (size_t)RT_X * NCHUNK * A_Q;        // 20348928
}

// ---------------- scratch (device globals; zero-initialized) ----------------
__device__ float g_gi0[(size_t)MB_ * G_];
__device__ float g_gh0[(size_t)MRP * G_];
__device__ float g_gi1[(size_t)MRP * G_];
__device__ float g_gh1[(size_t)MRP * G_];
__device__ float g_h0s[(size_t)MRP * D_];   // fp32 state (pad rows stay 0)
__device__ float g_h1s[(size_t)MRP * D_];
__device__ uint4 g_h0p[HQ];                 // packed state (pads stay 0)
__device__ uint4 g_h1p[HQ];
__device__ uint4 g_xp[XQ];                  // packed x
__device__ uint4 g_Wp[4 * WQ_PER_W];        // packed Wi0,Wi1,Wh0,Wh1

// ---------------- helpers ----------------
__device__ __forceinline__ uint32_t smem_u32(const void* p) {
    uint32_t a;
    asm("{ .reg .u64 t; cvta.to.shared.u64 t, %1; cvt.u32.u64 %0, t; }"
        : "=r"(a) : "l"(p));
    return a;
}
#define CP_ASYNC16(dst, src) \
    asm volatile("cp.async.cg.shared.global [%0], [%1], 16;" :: "r"(dst), "l"(src))
#define CP_COMMIT() asm volatile("cp.async.commit_group;" ::: "memory")
template <int N>
__device__ __forceinline__ void cp_wait() {
    asm volatile("cp.async.wait_group %0;" :: "n"(N) : "memory");
}

__device__ __forceinline__ uint32_t cvt_tf32(float x) {
    uint32_t r;
    asm("cvt.rna.tf32.f32 %0, %1;" : "=r"(r) : "f"(x));
    return r;
}
__device__ __forceinline__ void split_tf32(float x, uint32_t& hi, uint32_t& lo) {
    hi = cvt_tf32(x);
    lo = cvt_tf32(x - __uint_as_float(hi));
}

#define MMA_TF32(d, a, b0, b1)                                              \
    asm volatile("mma.sync.aligned.m16n8k8.row.col.f32.tf32.tf32.f32 "      \
        "{%0,%1,%2,%3}, {%4,%5,%6,%7}, {%8,%9}, {%0,%1,%2,%3};"             \
        : "+f"((d)[0]), "+f"((d)[1]), "+f"((d)[2]), "+f"((d)[3])            \
        : "r"((a)[0]), "r"((a)[1]), "r"((a)[2]), "r"((a)[3]),               \
          "r"(b0), "r"(b1))

// ---------------------------------------------------------------------------
// Packed-activation writer (A layout): per (rowtile rt, chunk ch): 1024 quads,
// hi at (mg*2+k8)*32+lane, lo at +512. quad comps s: 0:(r,kk) 1:(r+8,kk)
// 2:(r,kk+4) 3:(r+8,kk+4)
// ---------------------------------------------------------------------------
__device__ __forceinline__ void write_packed4(uint32_t* Ap, int m, int d0,
                                              const uint32_t* hi,
                                              const uint32_t* lo) {
    int rt = m >> 7, mrow = m & 127;
    int mg = mrow >> 4, rr = mrow & 15;
    int ch = d0 >> 4, kd = d0 & 15;
    int k8 = kd >> 3, chalf = (kd & 7) >> 2;
    int s = (rr >> 3) + chalf * 2;
    int lane0 = (rr & 7) * 4;
    size_t qhi = ((size_t)rt * NCHUNK + ch) * A_Q + (mg * 2 + k8) * 32 + lane0;
#pragma unroll
    for (int j = 0; j < 4; j++) {
        Ap[(qhi + j) * 4 + s]       = hi[j];
        Ap[(qhi + 512 + j) * 4 + s] = lo[j];
    }
}

// ---------------------------------------------------------------------------
// GEMM core: C tile (128x64) = A[rt] @ W[ct]^T + bias. 256 thr, 8 warps
// (warpM 0..3 x warpN 0..1, 32 cols each). Pure LDS.128 + HMMA mainloop.
// ---------------------------------------------------------------------------
__device__ __forceinline__ void load_stage(uint32_t sS, const uint4* __restrict__ Aq,
                                           const uint4* __restrict__ Bq,
                                           int ch, int tid) {
    const uint4* a = Aq + (size_t)ch * A_Q;
    const uint4* b = Bq + (size_t)ch * B_Q;
#pragma unroll
    for (int i = 0; i < 4; i++) {
        int s = tid + i * 256;
        CP_ASYNC16(sS + (uint32_t)s * 16u, a + s);
    }
#pragma unroll
    for (int i = 0; i < 2; i++) {
        int s = tid + i * 256;
        CP_ASYNC16(sS + (uint32_t)(A_Q + s) * 16u, b + s);
    }
}

__device__ __forceinline__ void tf32_gemm_core(const uint4* __restrict__ Ap,
                                               const uint4* __restrict__ Wp,
                                               const float* __restrict__ bias,
                                               float* __restrict__ C) {
    extern __shared__ uint4 smq[];

    const int tid  = threadIdx.x;
    const int lane = tid & 31, warp = tid >> 5;
    const int warpM = warp & 3, warpN = warp >> 2;
    const int r  = lane >> 2;
    const int qk = lane & 3;

    const uint4* Aq = Ap + (size_t)blockIdx.y * (NCHUNK * A_Q);
    const uint4* Bq = Wp + (size_t)blockIdx.x * (NCHUNK * B_Q);

    float acc[2][4][4];
#pragma unroll
    for (int mt = 0; mt < 2; mt++)
#pragma unroll
        for (int nt = 0; nt < 4; nt++)
#pragma unroll
            for (int i = 0; i < 4; i++) acc[mt][nt][i] = 0.f;

    uint32_t sb = smem_u32(smq);
    load_stage(sb, Aq, Bq, 0, tid);
    CP_COMMIT();
    load_stage(sb + STAGE_Q * 16, Aq, Bq, 1, tid);
    CP_COMMIT();

    for (int ch = 0; ch < NCHUNK; ch++) {
        if (ch < NCHUNK - 1) cp_wait<1>(); else cp_wait<0>();
        __syncthreads();
        if (ch + 2 < NCHUNK) {
            load_stage(sb + ((ch + 2) % STAGES) * (STAGE_Q * 16), Aq, Bq, ch + 2, tid);
            CP_COMMIT();
        }
        const uint4* As = smq + (size_t)(ch % STAGES) * STAGE_Q;
        const uint4* Bs = As + A_Q;

#pragma unroll
        for (int k8 = 0; k8 < 2; k8++) {
            uint4 ah[2], al[2];
#pragma unroll
            for (int mt = 0; mt < 2; mt++) {
                int mg = warpM * 2 + mt;
                int ai = (mg * 2 + k8) * 32 + lane;
                ah[mt] = As[ai];
                al[mt] = As[ai + 512];
            }
            uint4 bf[4];
#pragma unroll
            for (int j = 0; j < 4; j++) {
                int g = warpN * 4 + j;
                bf[j] = Bs[(g * 2 + k8) * 32 + lane];
            }
            // pass 1: al * bh
#pragma unroll
            for (int j = 0; j < 4; j++)
#pragma unroll
                for (int mt = 0; mt < 2; mt++)
                    MMA_TF32(acc[mt][j], ((const uint32_t*)&al[mt]),
                             bf[j].x, bf[j].y);
            // pass 2: ah * bl
#pragma unroll
            for (int j = 0; j < 4; j++)
#pragma unroll
                for (int mt = 0; mt < 2; mt++)
                    MMA_TF32(acc[mt][j], ((const uint32_t*)&ah[mt]),
                             bf[j].z, bf[j].w);
            // pass 3: ah * bh
#pragma unroll
            for (int j = 0; j < 4; j++)
#pragma unroll
                for (int mt = 0; mt < 2; mt++)
                    MMA_TF32(acc[mt][j], ((const uint32_t*)&ah[mt]),
                             bf[j].x, bf[j].y);
        }
    }

    // epilogue: acc + bias -> C (float2 stores)
    const int brow = blockIdx.y * 128;
    const int bcol = blockIdx.x * 64;
    const int q2 = qk * 2;
#pragma unroll
    for (int mt = 0; mt < 2; mt++) {
        const int row0 = brow + warpM * 32 + mt * 16 + r;
#pragma unroll
        for (int nt = 0; nt < 4; nt++) {
            const int col = bcol + warpN * 32 + nt * 8 + q2;
            const float2 bv = *reinterpret_cast<const float2*>(bias + col);
            float2 v0 = make_float2(acc[mt][nt][0] + bv.x, acc[mt][nt][1] + bv.y);
            float2 v1 = make_float2(acc[mt][nt][2] + bv.x, acc[mt][nt][3] + bv.y);
            *reinterpret_cast<float2*>(C + (size_t)row0 * G_ + col) = v0;
            *reinterpret_cast<float2*>(C + (size_t)(row0 + 8) * G_ + col) = v1;
        }
    }
}

__global__ void __launch_bounds__(256, 3)
tf32_gemm1_kernel(const uint4* __restrict__ Ap, const uint4* __restrict__ Wp,
                  const float* __restrict__ bias, float* __restrict__ C) {
    tf32_gemm_core(Ap, Wp, bias, C);
}

__global__ void __launch_bounds__(256, 3)
tf32_gemm3_kernel(const uint4* A0, const uint4* P0, const float* b0, float* C0,
                  const uint4* A1, const uint4* P1, const float* b1, float* C1,
                  const uint4* A2, const uint4* P2, const float* b2, float* C2) {
    const uint4* A; const uint4* P; const float* bias; float* C;
    if (blockIdx.z == 0)      { A = A0; P = P0; bias = b0; C = C0; }
    else if (blockIdx.z == 1) { A = A1; P = P1; bias = b1; C = C1; }
    else                      { A = A2; P = P2; bias = b2; C = C2; }
    tf32_gemm_core(A, P, bias, C);
}

// ---------------------------------------------------------------------------
// Weight prepack (BK=16, 64-col tiles): quad e=(g*2+k8)*32+lane holds
// [bh(kk),bh(kk+4),bl(kk),bl(kk+4)] for col g*8+(lane>>2), kk=k8*8+(lane&3).
// ---------------------------------------------------------------------------
__global__ void prepack_kernel(const float* __restrict__ Wi,
                               const float* __restrict__ Wh,
                               uint4* __restrict__ Wp) {
    __shared__ float tile[16][64];
    const int ct = blockIdx.x, ch = blockIdx.y, z = blockIdx.z;
    const float* src = (z < 2 ? Wi : Wh) + (size_t)(z & 1) * D_ * G_;
    const int tid = threadIdx.x;

#pragma unroll
    for (int i = 0; i < 4; i++) {
        int s = tid + i * 256;          // 0..1023
        int kk = s >> 6, n = s & 63;
        tile[kk][n] = src[(size_t)(ch * BK + kk) * G_ + ct * 64 + n];
    }
    __syncthreads();

    uint4* dst = Wp + ((size_t)z * CT_ + ct) * (NCHUNK * B_Q) + (size_t)ch * B_Q;
#pragma unroll
    for (int i = 0; i < 2; i++) {
        int e = tid + i * 256;          // 0..511
        int lane = e & 31, k8 = (e >> 5) & 1, g = e >> 6;
        int rr = lane >> 2, qq = lane & 3;
        int nl = g * 8 + rr;
        int kl = k8 * 8 + qq;
        uint32_t h0, l0, h1, l1;
        split_tf32(tile[kl][nl],     h0, l0);
        split_tf32(tile[kl + 4][nl], h1, l1);
        uint4 q; q.x = h0; q.y = h1; q.z = l0; q.w = l1;
        dst[e] = q;
    }
}

// ---------------------------------------------------------------------------
// x prepack: one block per row of x, packed into g_xp.
// ---------------------------------------------------------------------------
__global__ void xpack_kernel(const float* __restrict__ x, uint4* __restrict__ xp) {
    int m = blockIdx.x;
    int tid = threadIdx.x;
    float4 v = reinterpret_cast<const float4*>(x + (size_t)m * D_)[tid];
    uint32_t hi[4], lo[4];
    split_tf32(v.x, hi[0], lo[0]);
    split_tf32(v.y, hi[1], lo[1]);
    split_tf32(v.z, hi[2], lo[2]);
    split_tf32(v.w, hi[3], lo[3]);
    write_packed4((uint32_t*)xp, m, tid * 4, hi, lo);
}

// ---------------------------------------------------------------------------
// Fused GRU cell + LayerNorm (128 thr x float4 = 512 = D); writes fp32 state,
// packed state, and optionally the output tensor.
// ---------------------------------------------------------------------------
__device__ __forceinline__ float sigf(float v) { return 1.f / (1.f + expf(-v)); }

__device__ __forceinline__ void cell_body(const float* __restrict__ gi,
                                          const float* __restrict__ ghrow,
                                          float* __restrict__ hrow,
                                          uint32_t* __restrict__ hpack, int m,
                                          const float* __restrict__ gamma,
                                          const float* __restrict__ beta,
                                          float* __restrict__ o2) {
    const float4* gi4 = reinterpret_cast<const float4*>(gi);
    const float4* gh4 = reinterpret_cast<const float4*>(ghrow);
    float4* h4 = reinterpret_cast<float4*>(hrow);
    int tid = threadIdx.x;

    float4 ir = gi4[tid], iz = gi4[128 + tid], inn = gi4[256 + tid];
    float4 hr = gh4[tid], hz = gh4[128 + tid], hn = gh4[256 + tid];
    float4 hv = h4[tid];

    float o[4];
    {
        float rr, z, nv;
        rr = sigf(ir.x + hr.x); z = sigf(iz.x + hz.x); nv = tanhf(inn.x + rr * hn.x);
        o[0] = nv + z * (hv.x - nv);
        rr = sigf(ir.y + hr.y); z = sigf(iz.y + hz.y); nv = tanhf(inn.y + rr * hn.y);
        o[1] = nv + z * (hv.y - nv);
        rr = sigf(ir.z + hr.z); z = sigf(iz.z + hz.z); nv = tanhf(inn.z + rr * hn.z);
        o[2] = nv + z * (hv.z - nv);
        rr = sigf(ir.w + hr.w); z = sigf(iz.w + hz.w); nv = tanhf(inn.w + rr * hn.w);
        o[3] = nv + z * (hv.w - nv);
    }
    float s = o[0] + o[1] + o[2] + o[3];
    float s2 = o[0]*o[0] + o[1]*o[1] + o[2]*o[2] + o[3]*o[3];
#pragma unroll
    for (int off = 16; off > 0; off >>= 1) {
        s  += __shfl_xor_sync(0xffffffffu, s,  off);
        s2 += __shfl_xor_sync(0xffffffffu, s2, off);
    }
    __shared__ float sh[4], sh2[4];
    int w = tid >> 5;
    if ((tid & 31) == 0) { sh[w] = s; sh2[w] = s2; }
    __syncthreads();
    s  = sh[0]  + sh[1]  + sh[2]  + sh[3];
    s2 = sh2[0] + sh2[1] + sh2[2] + sh2[3];
    float mu  = s * (1.f / D_);
    float var = s2 * (1.f / D_) - mu * mu;
    float inv = rsqrtf(var + 1e-5f);

    const float4 g4 = reinterpret_cast<const float4*>(gamma)[tid];
    const float4 b4 = reinterpret_cast<const float4*>(beta)[tid];
    float y[4];
    y[0] = (o[0] - mu) * inv * g4.x + b4.x;
    y[1] = (o[1] - mu) * inv * g4.y + b4.y;
    y[2] = (o[2] - mu) * inv * g4.z + b4.z;
    y[3] = (o[3] - mu) * inv * g4.w + b4.w;
    h4[tid] = make_float4(y[0], y[1], y[2], y[3]);
    uint32_t hi[4], lo[4];
#pragma unroll
    for (int j = 0; j < 4; j++) split_tf32(y[j], hi[j], lo[j]);
    write_packed4(hpack, m, tid * 4, hi, lo);
    if (o2) reinterpret_cast<float4*>(o2)[tid] =
        make_float4(y[0], y[1], y[2], y[3]);
}

// single cell (cell0 at t=0)
__global__ void __launch_bounds__(128)
gru_cell(const float* __restrict__ gi_base, int t,
         const float* __restrict__ gh, float* __restrict__ h,
         uint32_t* __restrict__ hpack,
         const float* __restrict__ gamma, const float* __restrict__ beta) {
    int m = blockIdx.x;
    int b = m / N_, n = m % N_;
    const float* gi = gi_base + ((size_t)(b * T_ + t) * N_ + n) * G_;
    cell_body(gi, gh + (size_t)m * G_, h + (size_t)m * D_, hpack, m,
              gamma, beta, nullptr);
}

// merged per-timestep cells: z=0 -> cell1(t) (writes out), z=1 -> cell0(t+1)
__global__ void __launch_bounds__(128)
gru_cell2(const float* __restrict__ gi0_base, const float* __restrict__ gi1,
          int tnext,
          const float* __restrict__ gh0, const float* __restrict__ gh1,
          float* __restrict__ h0s, float* __restrict__ h1s,
          uint32_t* __restrict__ h0p, uint32_t* __restrict__ h1p,
          const float* __restrict__ gamma, const float* __restrict__ beta,
          float* __restrict__ out, int t_out) {
    int m = blockIdx.x;
    int b = m / N_, n = m % N_;
    if (blockIdx.z == 0) {
        float* o2 = out + ((size_t)(b * T_ + t_out) * N_ + n) * D_;
        cell_body(gi1 + (size_t)m * G_, gh1 + (size_t)m * G_,
                  h1s + (size_t)m * D_, h1p, m, gamma + D_, beta + D_, o2);
    } else {
        const float* gi = gi0_base + ((size_t)(b * T_ + tnext) * N_ + n) * G_;
        cell_body(gi, gh0 + (size_t)m * G_, h0s + (size_t)m * D_, h0p, m,
                  gamma, beta, nullptr);
    }
}

// ---------------------------------------------------------------------------
__global__ void init_h_kernel(const float* __restrict__ h0,
                              float* __restrict__ h0s, float* __restrict__ h1s,
                              uint32_t* __restrict__ h0p,
                              uint32_t* __restrict__ h1p) {
    int row = blockIdx.x;
    int n = row % N_;
    int l = (row / N_) % 2;
    int b = row / (2 * N_);
    int tid = threadIdx.x;
    int m = b * N_ + n;
    float4 v = reinterpret_cast<const float4*>(h0 + (size_t)row * D_)[tid];
    float* hs = (l == 0) ? h0s : h1s;
    reinterpret_cast<float4*>(hs + (size_t)m * D_)[tid] = v;
    uint32_t hi[4], lo[4];
    split_tf32(v.x, hi[0], lo[0]);
    split_tf32(v.y, hi[1], lo[1]);
    split_tf32(v.z, hi[2], lo[2]);
    split_tf32(v.w, hi[3], lo[3]);
    write_packed4((l == 0) ? h0p : h1p, m, tid * 4, hi, lo);
}

__global__ void write_hidden_kernel(const float* __restrict__ h0s,
                                    const float* __restrict__ h1s,
                                    float* __restrict__ dst) {
    int i = blockIdx.x * blockDim.x + threadIdx.x;
    if (i >= 2 * MR * D_) return;
    int d = i % D_;
    int r = i / D_;
    int n = r % N_; r /= N_;
    int l = r % 2;
    int b = r / 2;
    const float* src = (l == 0) ? h0s : h1s;
    dst[i] = src[((size_t)b * N_ + n) * D_ + d];
}

// ---------------------------------------------------------------------------
extern "C" void kernel_launch(void* const* d_in, const int* in_sizes, int n_in,
                              void* d_out, int out_size) {
    (void)in_sizes; (void)n_in;
    const float* x     = (const float*)d_in[0];
    const float* h0    = (const float*)d_in[1];
    const float* Wi    = (const float*)d_in[2];
    const float* bi    = (const float*)d_in[3];
    const float* Wh    = (const float*)d_in[4];
    const float* bh    = (const float*)d_in[5];
    const float* gamma = (const float*)d_in[6];
    const float* beta  = (const float*)d_in[7];
    float* out = (float*)d_out;

    float *gi0, *gh0, *gi1, *gh1, *h0s, *h1s;
    uint4 *h0p, *h1p, *xp, *Wp;
    cudaGetSymbolAddress((void**)&gi0, g_gi0);
    cudaGetSymbolAddress((void**)&gh0, g_gh0);
    cudaGetSymbolAddress((void**)&gi1, g_gi1);
    cudaGetSymbolAddress((void**)&gh1, g_gh1);
    cudaGetSymbolAddress((void**)&h0s, g_h0s);
    cudaGetSymbolAddress((void**)&h1s, g_h1s);
    cudaGetSymbolAddress((void**)&h0p, g_h0p);
    cudaGetSymbolAddress((void**)&h1p, g_h1p);
    cudaGetSymbolAddress((void**)&xp,  g_xp);
    cudaGetSymbolAddress((void**)&Wp,  g_Wp);

    cudaFuncSetAttribute(tf32_gemm1_kernel,
                         cudaFuncAttributeMaxDynamicSharedMemorySize, SMEM_BYTES);
    cudaFuncSetAttribute(tf32_gemm3_kernel,
                         cudaFuncAttributeMaxDynamicSharedMemorySize, SMEM_BYTES);

    const uint4* Wi0p = Wp;
    const uint4* Wi1p = Wp + WQ_PER_W;
    const uint4* Wh0p = Wp + 2 * WQ_PER_W;
    const uint4* Wh1p = Wp + 3 * WQ_PER_W;

    prepack_kernel<<<dim3(CT_, NCHUNK, 4), 256>>>(Wi, Wh, Wp);
    init_h_kernel<<<2 * MR, 128>>>(h0, h0s, h1s, (uint32_t*)h0p, (uint32_t*)h1p);
    xpack_kernel<<<MB_, 128>>>(x, xp);

    // Hoisted layer-0 input GEMM (all timesteps): gi0 = x @ Wi0 + bi0
    tf32_gemm1_kernel<<<dim3(CT_, RT_X), 256, SMEM_BYTES>>>(xp, Wi0p, bi, gi0);

    // GH0(0) = h0 @ Wh0 + bh0, then cell0(0)
    tf32_gemm1_kernel<<<dim3(CT_, RT_R), 256, SMEM_BYTES>>>(h0p, Wh0p, bh, gh0);
    gru_cell<<<MR, 128>>>(gi0, 0, gh0, h0s, (uint32_t*)h0p, gamma, beta);

    for (int t = 0; t < T_; t++) {
        int nz_g = (t == T_ - 1) ? 2 : 3;
        // z=0: GI1(t)=out0(t)@Wi1 ; z=1: GH1(t)=h1@Wh1 ; z=2: GH0(t+1)=out0(t)@Wh0
        tf32_gemm3_kernel<<<dim3(CT_, RT_R, nz_g), 256, SMEM_BYTES>>>(
            h0p, Wi1p, bi + G_, gi1,
            h1p, Wh1p, bh + G_, gh1,
            h0p, Wh0p, bh,      gh0);
        int nz_c = (t == T_ - 1) ? 1 : 2;
        gru_cell2<<<dim3(MR, 1, nz_c), 128>>>(gi0, gi1, t + 1, gh0, gh1,
                                              h0s, h1s,
                                              (uint32_t*)h0p, (uint32_t*)h1p,
                                              gamma, beta, out, t);
    }

    long long need = (long long)MB_ * D_ + (long long)2 * MR * D_;
    if ((long long)out_size >= need) {
        int tot = 2 * MR * D_;
        write_hidden_kernel<<<(tot + 255) / 256, 256>>>(h0s, h1s,
                                                        out + (size_t)MB_ * D_);
    }
}

// round 9
// speedup vs baseline: 1.2075x; 1.0299x over previous
#include <cuda_runtime.h>
#include <math.h>
#include <stdint.h>

// GraphRNN: 2-layer LayerNorm-GRU scan. B=16, T=24, N=207, D=512, G=1536.
// R9: R8 GEMM core (pre-split tf32 hi/lo packed, 128x64 @ 3 CTAs/SM) +
//     t-major gi0 layout + big-GEMM slices overlapped on a low-priority
//     stream, gated per-timestep by events.
namespace {
constexpr int B_ = 16, T_ = 24, N_ = 207, D_ = 512, G_ = 1536;
constexpr int MR  = B_ * N_;        // 3312 rows per timestep
constexpr int MRP = 3328;           // padded: 26*128
constexpr int MB_ = B_ * T_ * N_;   // 79488

constexpr int BK = 16;              // k-chunk
constexpr int NCHUNK = D_ / BK;     // 32
constexpr int CT_ = G_ / 64;        // 24 col-tiles of 64
constexpr int RT_R = MRP / 128;     // 26 row-tiles per timestep

constexpr int A_Q = 1024, B_Q = 512;
constexpr int STAGE_Q = A_Q + B_Q;  // 1536 quads = 24KB
constexpr int STAGES = 3;
constexpr int SMEM_BYTES = STAGES * STAGE_Q * 16;  // 73728

constexpr size_t WQ_PER_W = (size_t)CT_ * NCHUNK * B_Q;        // 393216
constexpr size_t HQ  = (size_t)RT_R * NCHUNK * A_Q;            // per-t packed rows
constexpr size_t XQ  = (size_t)T_ * HQ;                        // t-major packed x
constexpr size_t SLICE_Q = HQ;                                 // quads per t-slice
}

// ---------------- scratch (device globals; zero-initialized) ----------------
__device__ float g_gi0[(size_t)T_ * MRP * G_];   // t-major
__device__ float g_gh0[(size_t)MRP * G_];
__device__ float g_gi1[(size_t)MRP * G_];
__device__ float g_gh1[(size_t)MRP * G_];
__device__ float g_h0s[(size_t)MRP * D_];
__device__ float g_h1s[(size_t)MRP * D_];
__device__ uint4 g_h0p[HQ];
__device__ uint4 g_h1p[HQ];
__device__ uint4 g_xp[XQ];                       // t-major packed x
__device__ uint4 g_Wp[4 * WQ_PER_W];

// ---------------- helpers ----------------
__device__ __forceinline__ uint32_t smem_u32(const void* p) {
    uint32_t a;
    asm("{ .reg .u64 t; cvta.to.shared.u64 t, %1; cvt.u32.u64 %0, t; }"
        : "=r"(a) : "l"(p));
    return a;
}
#define CP_ASYNC16(dst, src) \
    asm volatile("cp.async.cg.shared.global [%0], [%1], 16;" :: "r"(dst), "l"(src))
#define CP_COMMIT() asm volatile("cp.async.commit_group;" ::: "memory")
template <int N>
__device__ __forceinline__ void cp_wait() {
    asm volatile("cp.async.wait_group %0;" :: "n"(N) : "memory");
}

__device__ __forceinline__ uint32_t cvt_tf32(float x) {
    uint32_t r;
    asm("cvt.rna.tf32.f32 %0, %1;" : "=r"(r) : "f"(x));
    return r;
}
__device__ __forceinline__ void split_tf32(float x, uint32_t& hi, uint32_t& lo) {
    hi = cvt_tf32(x);
    lo = cvt_tf32(x - __uint_as_float(hi));
}

#define MMA_TF32(d, a, b0, b1)                                              \
    asm volatile("mma.sync.aligned.m16n8k8.row.col.f32.tf32.tf32.f32 "      \
        "{%0,%1,%2,%3}, {%4,%5,%6,%7}, {%8,%9}, {%0,%1,%2,%3};"             \
        : "+f"((d)[0]), "+f"((d)[1]), "+f"((d)[2]), "+f"((d)[3])            \
        : "r"((a)[0]), "r"((a)[1]), "r"((a)[2]), "r"((a)[3]),               \
          "r"(b0), "r"(b1))

// ---------------------------------------------------------------------------
// Packed-activation writer (A layout per rowtile,chunk: 1024 quads,
// hi at (mg*2+k8)*32+lane, lo at +512).
// ---------------------------------------------------------------------------
__device__ __forceinline__ void write_packed4(uint32_t* Ap, int m, int d0,
                                              const uint32_t* hi,
                                              const uint32_t* lo) {
    int rt = m >> 7, mrow = m & 127;
    int mg = mrow >> 4, rr = mrow & 15;
    int ch = d0 >> 4, kd = d0 & 15;
    int k8 = kd >> 3, chalf = (kd & 7) >> 2;
    int s = (rr >> 3) + chalf * 2;
    int lane0 = (rr & 7) * 4;
    size_t qhi = ((size_t)rt * NCHUNK + ch) * A_Q + (mg * 2 + k8) * 32 + lane0;
#pragma unroll
    for (int j = 0; j < 4; j++) {
        Ap[(qhi + j) * 4 + s]       = hi[j];
        Ap[(qhi + 512 + j) * 4 + s] = lo[j];
    }
}

// ---------------------------------------------------------------------------
// GEMM core (128x64 C tile), pure LDS.128 + HMMA.
// ---------------------------------------------------------------------------
__device__ __forceinline__ void load_stage(uint32_t sS, const uint4* __restrict__ Aq,
                                           const uint4* __restrict__ Bq,
                                           int ch, int tid) {
    const uint4* a = Aq + (size_t)ch * A_Q;
    const uint4* b = Bq + (size_t)ch * B_Q;
#pragma unroll
    for (int i = 0; i < 4; i++) {
        int s = tid + i * 256;
        CP_ASYNC16(sS + (uint32_t)s * 16u, a + s);
    }
#pragma unroll
    for (int i = 0; i < 2; i++) {
        int s = tid + i * 256;
        CP_ASYNC16(sS + (uint32_t)(A_Q + s) * 16u, b + s);
    }
}

__device__ __forceinline__ void tf32_gemm_core(const uint4* __restrict__ Ap,
                                               const uint4* __restrict__ Wp,
                                               const float* __restrict__ bias,
                                               float* __restrict__ C) {
    extern __shared__ uint4 smq[];

    const int tid  = threadIdx.x;
    const int lane = tid & 31, warp = tid >> 5;
    const int warpM = warp & 3, warpN = warp >> 2;
    const int r  = lane >> 2;
    const int qk = lane & 3;

    const uint4* Aq = Ap + (size_t)blockIdx.y * (NCHUNK * A_Q);
    const uint4* Bq = Wp + (size_t)blockIdx.x * (NCHUNK * B_Q);

    float acc[2][4][4];
#pragma unroll
    for (int mt = 0; mt < 2; mt++)
#pragma unroll
        for (int nt = 0; nt < 4; nt++)
#pragma unroll
            for (int i = 0; i < 4; i++) acc[mt][nt][i] = 0.f;

    uint32_t sb = smem_u32(smq);
    load_stage(sb, Aq, Bq, 0, tid);
    CP_COMMIT();
    load_stage(sb + STAGE_Q * 16, Aq, Bq, 1, tid);
    CP_COMMIT();

    for (int ch = 0; ch < NCHUNK; ch++) {
        if (ch < NCHUNK - 1) cp_wait<1>(); else cp_wait<0>();
        __syncthreads();
        if (ch + 2 < NCHUNK) {
            load_stage(sb + ((ch + 2) % STAGES) * (STAGE_Q * 16), Aq, Bq, ch + 2, tid);
            CP_COMMIT();
        }
        const uint4* As = smq + (size_t)(ch % STAGES) * STAGE_Q;
        const uint4* Bs = As + A_Q;

#pragma unroll
        for (int k8 = 0; k8 < 2; k8++) {
            uint4 ah[2], al[2];
#pragma unroll
            for (int mt = 0; mt < 2; mt++) {
                int mg = warpM * 2 + mt;
                int ai = (mg * 2 + k8) * 32 + lane;
                ah[mt] = As[ai];
                al[mt] = As[ai + 512];
            }
            uint4 bf[4];
#pragma unroll
            for (int j = 0; j < 4; j++) {
                int g = warpN * 4 + j;
                bf[j] = Bs[(g * 2 + k8) * 32 + lane];
            }
#pragma unroll
            for (int j = 0; j < 4; j++)
#pragma unroll
                for (int mt = 0; mt < 2; mt++)
                    MMA_TF32(acc[mt][j], ((const uint32_t*)&al[mt]),
                             bf[j].x, bf[j].y);
#pragma unroll
            for (int j = 0; j < 4; j++)
#pragma unroll
                for (int mt = 0; mt < 2; mt++)
                    MMA_TF32(acc[mt][j], ((const uint32_t*)&ah[mt]),
                             bf[j].z, bf[j].w);
#pragma unroll
            for (int j = 0; j < 4; j++)
#pragma unroll
                for (int mt = 0; mt < 2; mt++)
                    MMA_TF32(acc[mt][j], ((const uint32_t*)&ah[mt]),
                             bf[j].x, bf[j].y);
        }
    }

    const int brow = blockIdx.y * 128;
    const int bcol = blockIdx.x * 64;
    const int q2 = qk * 2;
#pragma unroll
    for (int mt = 0; mt < 2; mt++) {
        const int row0 = brow + warpM * 32 + mt * 16 + r;
#pragma unroll
        for (int nt = 0; nt < 4; nt++) {
            const int col = bcol + warpN * 32 + nt * 8 + q2;
            const float2 bv = *reinterpret_cast<const float2*>(bias + col);
            float2 v0 = make_float2(acc[mt][nt][0] + bv.x, acc[mt][nt][1] + bv.y);
            float2 v1 = make_float2(acc[mt][nt][2] + bv.x, acc[mt][nt][3] + bv.y);
            *reinterpret_cast<float2*>(C + (size_t)row0 * G_ + col) = v0;
            *reinterpret_cast<float2*>(C + (size_t)(row0 + 8) * G_ + col) = v1;
        }
    }
}

__global__ void __launch_bounds__(256, 3)
tf32_gemm1_kernel(const uint4* __restrict__ Ap, const uint4* __restrict__ Wp,
                  const float* __restrict__ bias, float* __restrict__ C) {
    tf32_gemm_core(Ap, Wp, bias, C);
}

__global__ void __launch_bounds__(256, 3)
tf32_gemm3_kernel(const uint4* A0, const uint4* P0, const float* b0, float* C0,
                  const uint4* A1, const uint4* P1, const float* b1, float* C1,
                  const uint4* A2, const uint4* P2, const float* b2, float* C2) {
    const uint4* A; const uint4* P; const float* bias; float* C;
    if (blockIdx.z == 0)      { A = A0; P = P0; bias = b0; C = C0; }
    else if (blockIdx.z == 1) { A = A1; P = P1; bias = b1; C = C1; }
    else                      { A = A2; P = P2; bias = b2; C = C2; }
    tf32_gemm_core(A, P, bias, C);
}

// ---------------------------------------------------------------------------
// Weight prepack (BK=16, 64-col tiles)
// ---------------------------------------------------------------------------
__global__ void prepack_kernel(const float* __restrict__ Wi,
                               const float* __restrict__ Wh,
                               uint4* __restrict__ Wp) {
    __shared__ float tile[16][64];
    const int ct = blockIdx.x, ch = blockIdx.y, z = blockIdx.z;
    const float* src = (z < 2 ? Wi : Wh) + (size_t)(z & 1) * D_ * G_;
    const int tid = threadIdx.x;

#pragma unroll
    for (int i = 0; i < 4; i++) {
        int s = tid + i * 256;
        int kk = s >> 6, n = s & 63;
        tile[kk][n] = src[(size_t)(ch * BK + kk) * G_ + ct * 64 + n];
    }
    __syncthreads();

    uint4* dst = Wp + ((size_t)z * CT_ + ct) * (NCHUNK * B_Q) + (size_t)ch * B_Q;
#pragma unroll
    for (int i = 0; i < 2; i++) {
        int e = tid + i * 256;
        int lane = e & 31, k8 = (e >> 5) & 1, g = e >> 6;
        int rr = lane >> 2, qq = lane & 3;
        int nl = g * 8 + rr;
        int kl = k8 * 8 + qq;
        uint32_t h0, l0, h1, l1;
        split_tf32(tile[kl][nl],     h0, l0);
        split_tf32(tile[kl + 4][nl], h1, l1);
        uint4 q; q.x = h0; q.y = h1; q.z = l0; q.w = l1;
        dst[e] = q;
    }
}

// ---------------------------------------------------------------------------
// x prepack: x row (b,t,n) -> t-major packed row t*MRP + b*N + n
// ---------------------------------------------------------------------------
__global__ void xpack_kernel(const float* __restrict__ x, uint4* __restrict__ xp) {
    int min_ = blockIdx.x;              // (b*T+t)*N + n
    int n = min_ % N_;
    int t = (min_ / N_) % T_;
    int b = min_ / (N_ * T_);
    int m = t * MRP + b * N_ + n;
    int tid = threadIdx.x;
    float4 v = reinterpret_cast<const float4*>(x + (size_t)min_ * D_)[tid];
    uint32_t hi[4], lo[4];
    split_tf32(v.x, hi[0], lo[0]);
    split_tf32(v.y, hi[1], lo[1]);
    split_tf32(v.z, hi[2], lo[2]);
    split_tf32(v.w, hi[3], lo[3]);
    write_packed4((uint32_t*)xp, m, tid * 4, hi, lo);
}

// ---------------------------------------------------------------------------
// Fused GRU cell + LayerNorm
// ---------------------------------------------------------------------------
__device__ __forceinline__ float sigf(float v) { return 1.f / (1.f + expf(-v)); }

__device__ __forceinline__ void cell_body(const float* __restrict__ gi,
                                          const float* __restrict__ ghrow,
                                          float* __restrict__ hrow,
                                          uint32_t* __restrict__ hpack, int m,
                                          const float* __restrict__ gamma,
                                          const float* __restrict__ beta,
                                          float* __restrict__ o2) {
    const float4* gi4 = reinterpret_cast<const float4*>(gi);
    const float4* gh4 = reinterpret_cast<const float4*>(ghrow);
    float4* h4 = reinterpret_cast<float4*>(hrow);
    int tid = threadIdx.x;

    float4 ir = gi4[tid], iz = gi4[128 + tid], inn = gi4[256 + tid];
    float4 hr = gh4[tid], hz = gh4[128 + tid], hn = gh4[256 + tid];
    float4 hv = h4[tid];

    float o[4];
    {
        float rr, z, nv;
        rr = sigf(ir.x + hr.x); z = sigf(iz.x + hz.x); nv = tanhf(inn.x + rr * hn.x);
        o[0] = nv + z * (hv.x - nv);
        rr = sigf(ir.y + hr.y); z = sigf(iz.y + hz.y); nv = tanhf(inn.y + rr * hn.y);
        o[1] = nv + z * (hv.y - nv);
        rr = sigf(ir.z + hr.z); z = sigf(iz.z + hz.z); nv = tanhf(inn.z + rr * hn.z);
        o[2] = nv + z * (hv.z - nv);
        rr = sigf(ir.w + hr.w); z = sigf(iz.w + hz.w); nv = tanhf(inn.w + rr * hn.w);
        o[3] = nv + z * (hv.w - nv);
    }
    float s = o[0] + o[1] + o[2] + o[3];
    float s2 = o[0]*o[0] + o[1]*o[1] + o[2]*o[2] + o[3]*o[3];
#pragma unroll
    for (int off = 16; off > 0; off >>= 1) {
        s  += __shfl_xor_sync(0xffffffffu, s,  off);
        s2 += __shfl_xor_sync(0xffffffffu, s2, off);
    }
    __shared__ float sh[4], sh2[4];
    int w = tid >> 5;
    if ((tid & 31) == 0) { sh[w] = s; sh2[w] = s2; }
    __syncthreads();
    s  = sh[0]  + sh[1]  + sh[2]  + sh[3];
    s2 = sh2[0] + sh2[1] + sh2[2] + sh2[3];
    float mu  = s * (1.f / D_);
    float var = s2 * (1.f / D_) - mu * mu;
    float inv = rsqrtf(var + 1e-5f);

    const float4 g4 = reinterpret_cast<const float4*>(gamma)[tid];
    const float4 b4 = reinterpret_cast<const float4*>(beta)[tid];
    float y[4];
    y[0] = (o[0] - mu) * inv * g4.x + b4.x;
    y[1] = (o[1] - mu) * inv * g4.y + b4.y;
    y[2] = (o[2] - mu) * inv * g4.z + b4.z;
    y[3] = (o[3] - mu) * inv * g4.w + b4.w;
    h4[tid] = make_float4(y[0], y[1], y[2], y[3]);
    uint32_t hi[4], lo[4];
#pragma unroll
    for (int j = 0; j < 4; j++) split_tf32(y[j], hi[j], lo[j]);
    write_packed4(hpack, m, tid * 4, hi, lo);
    if (o2) reinterpret_cast<float4*>(o2)[tid] =
        make_float4(y[0], y[1], y[2], y[3]);
}

// single cell (cell0 at t=0); gi0 is t-major
__global__ void __launch_bounds__(128)
gru_cell(const float* __restrict__ gi0, int t,
         const float* __restrict__ gh, float* __restrict__ h,
         uint32_t* __restrict__ hpack,
         const float* __restrict__ gamma, const float* __restrict__ beta) {
    int m = blockIdx.x;
    const float* gi = gi0 + ((size_t)t * MRP + m) * G_;
    cell_body(gi, gh + (size_t)m * G_, h + (size_t)m * D_, hpack, m,
              gamma, beta, nullptr);
}

// merged per-timestep cells: z=0 -> cell1(t) (writes out), z=1 -> cell0(t+1)
__global__ void __launch_bounds__(128)
gru_cell2(const float* __restrict__ gi0, const float* __restrict__ gi1,
          int tnext,
          const float* __restrict__ gh0, const float* __restrict__ gh1,
          float* __restrict__ h0s, float* __restrict__ h1s,
          uint32_t* __restrict__ h0p, uint32_t* __restrict__ h1p,
          const float* __restrict__ gamma, const float* __restrict__ beta,
          float* __restrict__ out, int t_out) {
    int m = blockIdx.x;
    int b = m / N_, n = m % N_;
    if (blockIdx.z == 0) {
        float* o2 = out + ((size_t)(b * T_ + t_out) * N_ + n) * D_;
        cell_body(gi1 + (size_t)m * G_, gh1 + (size_t)m * G_,
                  h1s + (size_t)m * D_, h1p, m, gamma + D_, beta + D_, o2);
    } else {
        const float* gi = gi0 + ((size_t)tnext * MRP + m) * G_;
        cell_body(gi, gh0 + (size_t)m * G_, h0s + (size_t)m * D_, h0p, m,
                  gamma, beta, nullptr);
    }
}

// ---------------------------------------------------------------------------
__global__ void init_h_kernel(const float* __restrict__ h0,
                              float* __restrict__ h0s, float* __restrict__ h1s,
                              uint32_t* __restrict__ h0p,
                              uint32_t* __restrict__ h1p) {
    int row = blockIdx.x;
    int n = row % N_;
    int l = (row / N_) % 2;
    int b = row / (2 * N_);
    int tid = threadIdx.x;
    int m = b * N_ + n;
    float4 v = reinterpret_cast<const float4*>(h0 + (size_t)row * D_)[tid];
    float* hs = (l == 0) ? h0s : h1s;
    reinterpret_cast<float4*>(hs + (size_t)m * D_)[tid] = v;
    uint32_t hi[4], lo[4];
    split_tf32(v.x, hi[0], lo[0]);
    split_tf32(v.y, hi[1], lo[1]);
    split_tf32(v.z, hi[2], lo[2]);
    split_tf32(v.w, hi[3], lo[3]);
    write_packed4((l == 0) ? h0p : h1p, m, tid * 4, hi, lo);
}

__global__ void write_hidden_kernel(const float* __restrict__ h0s,
                                    const float* __restrict__ h1s,
                                    float* __restrict__ dst) {
    int i = blockIdx.x * blockDim.x + threadIdx.x;
    if (i >= 2 * MR * D_) return;
    int d = i % D_;
    int r = i / D_;
    int n = r % N_; r /= N_;
    int l = r % 2;
    int b = r / 2;
    const float* src = (l == 0) ? h0s : h1s;
    dst[i] = src[((size_t)b * N_ + n) * D_ + d];
}

// ---------------------------------------------------------------------------
extern "C" void kernel_launch(void* const* d_in, const int* in_sizes, int n_in,
                              void* d_out, int out_size) {
    (void)in_sizes; (void)n_in;
    const float* x     = (const float*)d_in[0];
    const float* h0    = (const float*)d_in[1];
    const float* Wi    = (const float*)d_in[2];
    const float* bi    = (const float*)d_in[3];
    const float* Wh    = (const float*)d_in[4];
    const float* bh    = (const float*)d_in[5];
    const float* gamma = (const float*)d_in[6];
    const float* beta  = (const float*)d_in[7];
    float* out = (float*)d_out;

    float *gi0, *gh0, *gi1, *gh1, *h0s, *h1s;
    uint4 *h0p, *h1p, *xp, *Wp;
    cudaGetSymbolAddress((void**)&gi0, g_gi0);
    cudaGetSymbolAddress((void**)&gh0, g_gh0);
    cudaGetSymbolAddress((void**)&gi1, g_gi1);
    cudaGetSymbolAddress((void**)&gh1, g_gh1);
    cudaGetSymbolAddress((void**)&h0s, g_h0s);
    cudaGetSymbolAddress((void**)&h1s, g_h1s);
    cudaGetSymbolAddress((void**)&h0p, g_h0p);
    cudaGetSymbolAddress((void**)&h1p, g_h1p);
    cudaGetSymbolAddress((void**)&xp,  g_xp);
    cudaGetSymbolAddress((void**)&Wp,  g_Wp);

    cudaFuncSetAttribute(tf32_gemm1_kernel,
                         cudaFuncAttributeMaxDynamicSharedMemorySize, SMEM_BYTES);
    cudaFuncSetAttribute(tf32_gemm3_kernel,
                         cudaFuncAttributeMaxDynamicSharedMemorySize, SMEM_BYTES);

    // lazy-init background stream (lowest priority) + per-slice events
    static cudaStream_t s_bg = nullptr;
    static cudaEvent_t  s_ev[T_];    // s_ev[0] = fork event; s_ev[t] = slice t done (t>=1)
    if (!s_bg) {
        int lo = 0, hi = 0;
        cudaDeviceGetStreamPriorityRange(&lo, &hi);   // lo = least priority
        cudaStreamCreateWithPriority(&s_bg, cudaStreamNonBlocking, lo);
        for (int i = 0; i < T_; i++)
            cudaEventCreateWithFlags(&s_ev[i], cudaEventDisableTiming);
    }

    const uint4* Wi0p = Wp;
    const uint4* Wi1p = Wp + WQ_PER_W;
    const uint4* Wh0p = Wp + 2 * WQ_PER_W;
    const uint4* Wh1p = Wp + 3 * WQ_PER_W;

    prepack_kernel<<<dim3(CT_, NCHUNK, 4), 256>>>(Wi, Wh, Wp);
    init_h_kernel<<<2 * MR, 128>>>(h0, h0s, h1s, (uint32_t*)h0p, (uint32_t*)h1p);
    xpack_kernel<<<MB_, 128>>>(x, xp);

    // fork: background stream computes gi0 slices 1..23 (t-major)
    cudaEventRecord(s_ev[0], 0);
    cudaStreamWaitEvent(s_bg, s_ev[0], 0);
    for (int t = 1; t < T_; t++) {
        tf32_gemm1_kernel<<<dim3(CT_, RT_R), 256, SMEM_BYTES, s_bg>>>(
            xp + (size_t)t * SLICE_Q, Wi0p, bi, gi0 + (size_t)t * MRP * G_);
        cudaEventRecord(s_ev[t], s_bg);
    }

    // main chain: gi0 slice 0, GH0(0), cell0(0)
    tf32_gemm1_kernel<<<dim3(CT_, RT_R), 256, SMEM_BYTES>>>(xp, Wi0p, bi, gi0);
    tf32_gemm1_kernel<<<dim3(CT_, RT_R), 256, SMEM_BYTES>>>(h0p, Wh0p, bh, gh0);
    gru_cell<<<MR, 128>>>(gi0, 0, gh0, h0s, (uint32_t*)h0p, gamma, beta);

    for (int t = 0; t < T_; t++) {
        int nz_g = (t == T_ - 1) ? 2 : 3;
        tf32_gemm3_kernel<<<dim3(CT_, RT_R, nz_g), 256, SMEM_BYTES>>>(
            h0p, Wi1p, bi + G_, gi1,
            h1p, Wh1p, bh + G_, gh1,
            h0p, Wh0p, bh,      gh0);
        int nz_c = (t == T_ - 1) ? 1 : 2;
        if (nz_c == 2)
            cudaStreamWaitEvent(0, s_ev[t + 1], 0);  // gi0 slice t+1 ready (joins fork)
        gru_cell2<<<dim3(MR, 1, nz_c), 128>>>(gi0, gi1, t + 1, gh0, gh1,
                                              h0s, h1s,
                                              (uint32_t*)h0p, (uint32_t*)h1p,
                                              gamma, beta, out, t);
    }

    long long need = (long long)MB_ * D_ + (long long)2 * MR * D_;
    if ((long long)out_size >= need) {
        int tot = 2 * MR * D_;
        write_hidden_kernel<<<(tot + 255) / 256, 256>>>(h0s, h1s,
                                                        out + (size_t)MB_ * D_);
    }
}

// round 10
// speedup vs baseline: 1.2090x; 1.0013x over previous
#include <cuda_runtime.h>
#include <math.h>
#include <stdint.h>

// GraphRNN: 2-layer LayerNorm-GRU scan. B=16, T=24, N=207, D=512, G=1536.
// R10: dataflow-decoupled streams. Critical layer-0 chain (GH0 gemm + cell0)
//      on a high-priority stream; layer-1 work (GI1/GH1 gemms + cell1) lags
//      on a second stream; gi0 slices on a background stream. h0p double-
//      buffered by timestep parity. GEMM core = R8 (pre-split tf32 hi/lo
//      packed, 128x64 tiles @ 3 CTAs/SM).
namespace {
constexpr int B_ = 16, T_ = 24, N_ = 207, D_ = 512, G_ = 1536;
constexpr int MR  = B_ * N_;        // 3312 rows per timestep
constexpr int MRP = 3328;           // padded: 26*128
constexpr int MB_ = B_ * T_ * N_;   // 79488

constexpr int BK = 16;              // k-chunk
constexpr int NCHUNK = D_ / BK;     // 32
constexpr int CT_ = G_ / 64;        // 24 col-tiles of 64
constexpr int RT_R = MRP / 128;     // 26 row-tiles per timestep

constexpr int A_Q = 1024, B_Q = 512;
constexpr int STAGE_Q = A_Q + B_Q;  // 1536 quads = 24KB
constexpr int STAGES = 3;
constexpr int SMEM_BYTES = STAGES * STAGE_Q * 16;  // 73728

constexpr size_t WQ_PER_W = (size_t)CT_ * NCHUNK * B_Q;        // 393216
constexpr size_t HQ  = (size_t)RT_R * NCHUNK * A_Q;            // packed rows / t
constexpr size_t XQ  = (size_t)T_ * HQ;                        // t-major packed x
}

// ---------------- scratch (device globals; zero-initialized) ----------------
__device__ float g_gi0[(size_t)T_ * MRP * G_];   // t-major
__device__ float g_gh0[(size_t)MRP * G_];
__device__ float g_gi1[(size_t)MRP * G_];
__device__ float g_gh1[(size_t)MRP * G_];
__device__ float g_h0s[(size_t)MRP * D_];
__device__ float g_h1s[(size_t)MRP * D_];
__device__ uint4 g_h0p[2 * HQ];                  // double-buffered (parity t&1)
__device__ uint4 g_h1p[HQ];
__device__ uint4 g_xp[XQ];                       // t-major packed x
__device__ uint4 g_Wp[4 * WQ_PER_W];

// ---------------- helpers ----------------
__device__ __forceinline__ uint32_t smem_u32(const void* p) {
    uint32_t a;
    asm("{ .reg .u64 t; cvta.to.shared.u64 t, %1; cvt.u32.u64 %0, t; }"
        : "=r"(a) : "l"(p));
    return a;
}
#define CP_ASYNC16(dst, src) \
    asm volatile("cp.async.cg.shared.global [%0], [%1], 16;" :: "r"(dst), "l"(src))
#define CP_COMMIT() asm volatile("cp.async.commit_group;" ::: "memory")
template <int N>
__device__ __forceinline__ void cp_wait() {
    asm volatile("cp.async.wait_group %0;" :: "n"(N) : "memory");
}

__device__ __forceinline__ uint32_t cvt_tf32(float x) {
    uint32_t r;
    asm("cvt.rna.tf32.f32 %0, %1;" : "=r"(r) : "f"(x));
    return r;
}
__device__ __forceinline__ void split_tf32(float x, uint32_t& hi, uint32_t& lo) {
    hi = cvt_tf32(x);
    lo = cvt_tf32(x - __uint_as_float(hi));
}

#define MMA_TF32(d, a, b0, b1)                                              \
    asm volatile("mma.sync.aligned.m16n8k8.row.col.f32.tf32.tf32.f32 "      \
        "{%0,%1,%2,%3}, {%4,%5,%6,%7}, {%8,%9}, {%0,%1,%2,%3};"             \
        : "+f"((d)[0]), "+f"((d)[1]), "+f"((d)[2]), "+f"((d)[3])            \
        : "r"((a)[0]), "r"((a)[1]), "r"((a)[2]), "r"((a)[3]),               \
          "r"(b0), "r"(b1))

// ---------------------------------------------------------------------------
// Packed-activation writer (A layout per rowtile,chunk: 1024 quads,
// hi at (mg*2+k8)*32+lane, lo at +512).
// ---------------------------------------------------------------------------
__device__ __forceinline__ void write_packed4(uint32_t* Ap, int m, int d0,
                                              const uint32_t* hi,
                                              const uint32_t* lo) {
    int rt = m >> 7, mrow = m & 127;
    int mg = mrow >> 4, rr = mrow & 15;
    int ch = d0 >> 4, kd = d0 & 15;
    int k8 = kd >> 3, chalf = (kd & 7) >> 2;
    int s = (rr >> 3) + chalf * 2;
    int lane0 = (rr & 7) * 4;
    size_t qhi = ((size_t)rt * NCHUNK + ch) * A_Q + (mg * 2 + k8) * 32 + lane0;
#pragma unroll
    for (int j = 0; j < 4; j++) {
        Ap[(qhi + j) * 4 + s]       = hi[j];
        Ap[(qhi + 512 + j) * 4 + s] = lo[j];
    }
}

// ---------------------------------------------------------------------------
// GEMM core (128x64 C tile), pure LDS.128 + HMMA.
// ---------------------------------------------------------------------------
__device__ __forceinline__ void load_stage(uint32_t sS, const uint4* __restrict__ Aq,
                                           const uint4* __restrict__ Bq,
                                           int ch, int tid) {
    const uint4* a = Aq + (size_t)ch * A_Q;
    const uint4* b = Bq + (size_t)ch * B_Q;
#pragma unroll
    for (int i = 0; i < 4; i++) {
        int s = tid + i * 256;
        CP_ASYNC16(sS + (uint32_t)s * 16u, a + s);
    }
#pragma unroll
    for (int i = 0; i < 2; i++) {
        int s = tid + i * 256;
        CP_ASYNC16(sS + (uint32_t)(A_Q + s) * 16u, b + s);
    }
}

__device__ __forceinline__ void tf32_gemm_core(const uint4* __restrict__ Ap,
                                               const uint4* __restrict__ Wp,
                                               const float* __restrict__ bias,
                                               float* __restrict__ C) {
    extern __shared__ uint4 smq[];

    const int tid  = threadIdx.x;
    const int lane = tid & 31, warp = tid >> 5;
    const int warpM = warp & 3, warpN = warp >> 2;
    const int r  = lane >> 2;
    const int qk = lane & 3;

    const uint4* Aq = Ap + (size_t)blockIdx.y * (NCHUNK * A_Q);
    const uint4* Bq = Wp + (size_t)blockIdx.x * (NCHUNK * B_Q);

    float acc[2][4][4];
#pragma unroll
    for (int mt = 0; mt < 2; mt++)
#pragma unroll
        for (int nt = 0; nt < 4; nt++)
#pragma unroll
            for (int i = 0; i < 4; i++) acc[mt][nt][i] = 0.f;

    uint32_t sb = smem_u32(smq);
    load_stage(sb, Aq, Bq, 0, tid);
    CP_COMMIT();
    load_stage(sb + STAGE_Q * 16, Aq, Bq, 1, tid);
    CP_COMMIT();

    for (int ch = 0; ch < NCHUNK; ch++) {
        if (ch < NCHUNK - 1) cp_wait<1>(); else cp_wait<0>();
        __syncthreads();
        if (ch + 2 < NCHUNK) {
            load_stage(sb + ((ch + 2) % STAGES) * (STAGE_Q * 16), Aq, Bq, ch + 2, tid);
            CP_COMMIT();
        }
        const uint4* As = smq + (size_t)(ch % STAGES) * STAGE_Q;
        const uint4* Bs = As + A_Q;

#pragma unroll
        for (int k8 = 0; k8 < 2; k8++) {
            uint4 ah[2], al[2];
#pragma unroll
            for (int mt = 0; mt < 2; mt++) {
                int mg = warpM * 2 + mt;
                int ai = (mg * 2 + k8) * 32 + lane;
                ah[mt] = As[ai];
                al[mt] = As[ai + 512];
            }
            uint4 bf[4];
#pragma unroll
            for (int j = 0; j < 4; j++) {
                int g = warpN * 4 + j;
                bf[j] = Bs[(g * 2 + k8) * 32 + lane];
            }
#pragma unroll
            for (int j = 0; j < 4; j++)
#pragma unroll
                for (int mt = 0; mt < 2; mt++)
                    MMA_TF32(acc[mt][j], ((const uint32_t*)&al[mt]),
                             bf[j].x, bf[j].y);
#pragma unroll
            for (int j = 0; j < 4; j++)
#pragma unroll
                for (int mt = 0; mt < 2; mt++)
                    MMA_TF32(acc[mt][j], ((const uint32_t*)&ah[mt]),
                             bf[j].z, bf[j].w);
#pragma unroll
            for (int j = 0; j < 4; j++)
#pragma unroll
                for (int mt = 0; mt < 2; mt++)
                    MMA_TF32(acc[mt][j], ((const uint32_t*)&ah[mt]),
                             bf[j].x, bf[j].y);
        }
    }

    const int brow = blockIdx.y * 128;
    const int bcol = blockIdx.x * 64;
    const int q2 = qk * 2;
#pragma unroll
    for (int mt = 0; mt < 2; mt++) {
        const int row0 = brow + warpM * 32 + mt * 16 + r;
#pragma unroll
        for (int nt = 0; nt < 4; nt++) {
            const int col = bcol + warpN * 32 + nt * 8 + q2;
            const float2 bv = *reinterpret_cast<const float2*>(bias + col);
            float2 v0 = make_float2(acc[mt][nt][0] + bv.x, acc[mt][nt][1] + bv.y);
            float2 v1 = make_float2(acc[mt][nt][2] + bv.x, acc[mt][nt][3] + bv.y);
            *reinterpret_cast<float2*>(C + (size_t)row0 * G_ + col) = v0;
            *reinterpret_cast<float2*>(C + (size_t)(row0 + 8) * G_ + col) = v1;
        }
    }
}

__global__ void __launch_bounds__(256, 3)
tf32_gemm1_kernel(const uint4* __restrict__ Ap, const uint4* __restrict__ Wp,
                  const float* __restrict__ bias, float* __restrict__ C) {
    tf32_gemm_core(Ap, Wp, bias, C);
}

// two GEMMs in one launch (layer-1: GI1 and GH1)
__global__ void __launch_bounds__(256, 3)
tf32_gemm2_kernel(const uint4* A0, const uint4* P0, const float* b0, float* C0,
                  const uint4* A1, const uint4* P1, const float* b1, float* C1) {
    const uint4* A; const uint4* P; const float* bias; float* C;
    if (blockIdx.z == 0) { A = A0; P = P0; bias = b0; C = C0; }
    else                 { A = A1; P = P1; bias = b1; C = C1; }
    tf32_gemm_core(A, P, bias, C);
}

// ---------------------------------------------------------------------------
// Weight prepack (BK=16, 64-col tiles)
// ---------------------------------------------------------------------------
__global__ void prepack_kernel(const float* __restrict__ Wi,
                               const float* __restrict__ Wh,
                               uint4* __restrict__ Wp) {
    __shared__ float tile[16][64];
    const int ct = blockIdx.x, ch = blockIdx.y, z = blockIdx.z;
    const float* src = (z < 2 ? Wi : Wh) + (size_t)(z & 1) * D_ * G_;
    const int tid = threadIdx.x;

#pragma unroll
    for (int i = 0; i < 4; i++) {
        int s = tid + i * 256;
        int kk = s >> 6, n = s & 63;
        tile[kk][n] = src[(size_t)(ch * BK + kk) * G_ + ct * 64 + n];
    }
    __syncthreads();

    uint4* dst = Wp + ((size_t)z * CT_ + ct) * (NCHUNK * B_Q) + (size_t)ch * B_Q;
#pragma unroll
    for (int i = 0; i < 2; i++) {
        int e = tid + i * 256;
        int lane = e & 31, k8 = (e >> 5) & 1, g = e >> 6;
        int rr = lane >> 2, qq = lane & 3;
        int nl = g * 8 + rr;
        int kl = k8 * 8 + qq;
        uint32_t h0, l0, h1, l1;
        split_tf32(tile[kl][nl],     h0, l0);
        split_tf32(tile[kl + 4][nl], h1, l1);
        uint4 q; q.x = h0; q.y = h1; q.z = l0; q.w = l1;
        dst[e] = q;
    }
}

// ---------------------------------------------------------------------------
// x prepack: x row (b,t,n) -> t-major packed row t*MRP + b*N + n
// ---------------------------------------------------------------------------
__global__ void xpack_kernel(const float* __restrict__ x, uint4* __restrict__ xp) {
    int min_ = blockIdx.x;              // (b*T+t)*N + n
    int n = min_ % N_;
    int t = (min_ / N_) % T_;
    int b = min_ / (N_ * T_);
    int m = t * MRP + b * N_ + n;
    int tid = threadIdx.x;
    float4 v = reinterpret_cast<const float4*>(x + (size_t)min_ * D_)[tid];
    uint32_t hi[4], lo[4];
    split_tf32(v.x, hi[0], lo[0]);
    split_tf32(v.y, hi[1], lo[1]);
    split_tf32(v.z, hi[2], lo[2]);
    split_tf32(v.w, hi[3], lo[3]);
    write_packed4((uint32_t*)xp, m, tid * 4, hi, lo);
}

// ---------------------------------------------------------------------------
// Fused GRU cell + LayerNorm
// ---------------------------------------------------------------------------
__device__ __forceinline__ float sigf(float v) { return 1.f / (1.f + expf(-v)); }

__device__ __forceinline__ void cell_body(const float* __restrict__ gi,
                                          const float* __restrict__ ghrow,
                                          float* __restrict__ hrow,
                                          uint32_t* __restrict__ hpack, int m,
                                          const float* __restrict__ gamma,
                                          const float* __restrict__ beta,
                                          float* __restrict__ o2) {
    const float4* gi4 = reinterpret_cast<const float4*>(gi);
    const float4* gh4 = reinterpret_cast<const float4*>(ghrow);
    float4* h4 = reinterpret_cast<float4*>(hrow);
    int tid = threadIdx.x;

    float4 ir = gi4[tid], iz = gi4[128 + tid], inn = gi4[256 + tid];
    float4 hr = gh4[tid], hz = gh4[128 + tid], hn = gh4[256 + tid];
    float4 hv = h4[tid];

    float o[4];
    {
        float rr, z, nv;
        rr = sigf(ir.x + hr.x); z = sigf(iz.x + hz.x); nv = tanhf(inn.x + rr * hn.x);
        o[0] = nv + z * (hv.x - nv);
        rr = sigf(ir.y + hr.y); z = sigf(iz.y + hz.y); nv = tanhf(inn.y + rr * hn.y);
        o[1] = nv + z * (hv.y - nv);
        rr = sigf(ir.z + hr.z); z = sigf(iz.z + hz.z); nv = tanhf(inn.z + rr * hn.z);
        o[2] = nv + z * (hv.z - nv);
        rr = sigf(ir.w + hr.w); z = sigf(iz.w + hz.w); nv = tanhf(inn.w + rr * hn.w);
        o[3] = nv + z * (hv.w - nv);
    }
    float s = o[0] + o[1] + o[2] + o[3];
    float s2 = o[0]*o[0] + o[1]*o[1] + o[2]*o[2] + o[3]*o[3];
#pragma unroll
    for (int off = 16; off > 0; off >>= 1) {
        s  += __shfl_xor_sync(0xffffffffu, s,  off);
        s2 += __shfl_xor_sync(0xffffffffu, s2, off);
    }
    __shared__ float sh[4], sh2[4];
    int w = tid >> 5;
    if ((tid & 31) == 0) { sh[w] = s; sh2[w] = s2; }
    __syncthreads();
    s  = sh[0]  + sh[1]  + sh[2]  + sh[3];
    s2 = sh2[0] + sh2[1] + sh2[2] + sh2[3];
    float mu  = s * (1.f / D_);
    float var = s2 * (1.f / D_) - mu * mu;
    float inv = rsqrtf(var + 1e-5f);

    const float4 g4 = reinterpret_cast<const float4*>(gamma)[tid];
    const float4 b4 = reinterpret_cast<const float4*>(beta)[tid];
    float y[4];
    y[0] = (o[0] - mu) * inv * g4.x + b4.x;
    y[1] = (o[1] - mu) * inv * g4.y + b4.y;
    y[2] = (o[2] - mu) * inv * g4.z + b4.z;
    y[3] = (o[3] - mu) * inv * g4.w + b4.w;
    h4[tid] = make_float4(y[0], y[1], y[2], y[3]);
    uint32_t hi[4], lo[4];
#pragma unroll
    for (int j = 0; j < 4; j++) split_tf32(y[j], hi[j], lo[j]);
    write_packed4(hpack, m, tid * 4, hi, lo);
    if (o2) reinterpret_cast<float4*>(o2)[tid] =
        make_float4(y[0], y[1], y[2], y[3]);
}

// layer-0 cell: gi0 t-major slice; writes h0s + packed h0p (given parity buf)
__global__ void __launch_bounds__(128)
gru_cell0(const float* __restrict__ gi0, int t,
          const float* __restrict__ gh, float* __restrict__ h,
          uint32_t* __restrict__ hpack,
          const float* __restrict__ gamma, const float* __restrict__ beta) {
    int m = blockIdx.x;
    const float* gi = gi0 + ((size_t)t * MRP + m) * G_;
    cell_body(gi, gh + (size_t)m * G_, h + (size_t)m * D_, hpack, m,
              gamma, beta, nullptr);
}

// layer-1 cell: writes out[:, t] + h1s + h1p
__global__ void __launch_bounds__(128)
gru_cell1(const float* __restrict__ gi1, const float* __restrict__ gh1,
          float* __restrict__ h1s, uint32_t* __restrict__ h1p,
          const float* __restrict__ gamma, const float* __restrict__ beta,
          float* __restrict__ out, int t) {
    int m = blockIdx.x;
    int b = m / N_, n = m % N_;
    float* o2 = out + ((size_t)(b * T_ + t) * N_ + n) * D_;
    cell_body(gi1 + (size_t)m * G_, gh1 + (size_t)m * G_,
              h1s + (size_t)m * D_, h1p, m, gamma + D_, beta + D_, o2);
}

// ---------------------------------------------------------------------------
__global__ void init_h_kernel(const float* __restrict__ h0,
                              float* __restrict__ h0s, float* __restrict__ h1s,
                              uint32_t* __restrict__ h0p_init,
                              uint32_t* __restrict__ h1p) {
    int row = blockIdx.x;
    int n = row % N_;
    int l = (row / N_) % 2;
    int b = row / (2 * N_);
    int tid = threadIdx.x;
    int m = b * N_ + n;
    float4 v = reinterpret_cast<const float4*>(h0 + (size_t)row * D_)[tid];
    float* hs = (l == 0) ? h0s : h1s;
    reinterpret_cast<float4*>(hs + (size_t)m * D_)[tid] = v;
    uint32_t hi[4], lo[4];
    split_tf32(v.x, hi[0], lo[0]);
    split_tf32(v.y, hi[1], lo[1]);
    split_tf32(v.z, hi[2], lo[2]);
    split_tf32(v.w, hi[3], lo[3]);
    write_packed4((l == 0) ? h0p_init : h1p, m, tid * 4, hi, lo);
}

__global__ void write_hidden_kernel(const float* __restrict__ h0s,
                                    const float* __restrict__ h1s,
                                    float* __restrict__ dst) {
    int i = blockIdx.x * blockDim.x + threadIdx.x;
    if (i >= 2 * MR * D_) return;
    int d = i % D_;
    int r = i / D_;
    int n = r % N_; r /= N_;
    int l = r % 2;
    int b = r / 2;
    const float* src = (l == 0) ? h0s : h1s;
    dst[i] = src[((size_t)b * N_ + n) * D_ + d];
}

// ---------------------------------------------------------------------------
extern "C" void kernel_launch(void* const* d_in, const int* in_sizes, int n_in,
                              void* d_out, int out_size) {
    (void)in_sizes; (void)n_in;
    const float* x     = (const float*)d_in[0];
    const float* h0    = (const float*)d_in[1];
    const float* Wi    = (const float*)d_in[2];
    const float* bi    = (const float*)d_in[3];
    const float* Wh    = (const float*)d_in[4];
    const float* bh    = (const float*)d_in[5];
    const float* gamma = (const float*)d_in[6];
    const float* beta  = (const float*)d_in[7];
    float* out = (float*)d_out;

    float *gi0, *gh0, *gi1, *gh1, *h0s, *h1s;
    uint4 *h0p, *h1p, *xp, *Wp;
    cudaGetSymbolAddress((void**)&gi0, g_gi0);
    cudaGetSymbolAddress((void**)&gh0, g_gh0);
    cudaGetSymbolAddress((void**)&gi1, g_gi1);
    cudaGetSymbolAddress((void**)&gh1, g_gh1);
    cudaGetSymbolAddress((void**)&h0s, g_h0s);
    cudaGetSymbolAddress((void**)&h1s, g_h1s);
    cudaGetSymbolAddress((void**)&h0p, g_h0p);
    cudaGetSymbolAddress((void**)&h1p, g_h1p);
    cudaGetSymbolAddress((void**)&xp,  g_xp);
    cudaGetSymbolAddress((void**)&Wp,  g_Wp);

    cudaFuncSetAttribute(tf32_gemm1_kernel,
                         cudaFuncAttributeMaxDynamicSharedMemorySize, SMEM_BYTES);
    cudaFuncSetAttribute(tf32_gemm2_kernel,
                         cudaFuncAttributeMaxDynamicSharedMemorySize, SMEM_BYTES);

    // lazy-init streams/events
    static cudaStream_t s_hi = nullptr, s_L1 = nullptr, s_bg = nullptr;
    static cudaEvent_t ev_fork, ev_hi_done, ev_L1_done;
    static cudaEvent_t ev_gi0[T_], ev_h0[T_], ev_gi1[T_];
    if (!s_hi) {
        int lo = 0, hi = 0;
        cudaDeviceGetStreamPriorityRange(&lo, &hi);  // hi = greatest priority
        cudaStreamCreateWithPriority(&s_hi, cudaStreamNonBlocking, hi);
        cudaStreamCreateWithPriority(&s_L1, cudaStreamNonBlocking, lo);
        cudaStreamCreateWithPriority(&s_bg, cudaStreamNonBlocking, lo);
        cudaEventCreateWithFlags(&ev_fork,    cudaEventDisableTiming);
        cudaEventCreateWithFlags(&ev_hi_done, cudaEventDisableTiming);
        cudaEventCreateWithFlags(&ev_L1_done, cudaEventDisableTiming);
        for (int i = 0; i < T_; i++) {
            cudaEventCreateWithFlags(&ev_gi0[i], cudaEventDisableTiming);
            cudaEventCreateWithFlags(&ev_h0[i],  cudaEventDisableTiming);
            cudaEventCreateWithFlags(&ev_gi1[i], cudaEventDisableTiming);
        }
    }

    const uint4* Wi0p = Wp;
    const uint4* Wi1p = Wp + WQ_PER_W;
    const uint4* Wh0p = Wp + 2 * WQ_PER_W;
    const uint4* Wh1p = Wp + 3 * WQ_PER_W;
    uint4* h0pb[2] = { h0p, h0p + HQ };

    // ---- prologue on stream 0 ----
    prepack_kernel<<<dim3(CT_, NCHUNK, 4), 256>>>(Wi, Wh, Wp);
    // initial state packed into h0p[1] (parity of "t = -1"); h1p single-buffer
    init_h_kernel<<<2 * MR, 128>>>(h0, h0s, h1s,
                                   (uint32_t*)h0pb[1], (uint32_t*)h1p);
    xpack_kernel<<<MB_, 128>>>(x, xp);

    cudaEventRecord(ev_fork, 0);
    cudaStreamWaitEvent(s_bg, ev_fork, 0);
    cudaStreamWaitEvent(s_hi, ev_fork, 0);

    // background: gi0 slices 1..T-1
    for (int t = 1; t < T_; t++) {
        tf32_gemm1_kernel<<<dim3(CT_, RT_R), 256, SMEM_BYTES, s_bg>>>(
            xp + (size_t)t * HQ, Wi0p, bi, gi0 + (size_t)t * MRP * G_);
        cudaEventRecord(ev_gi0[t], s_bg);
    }

    // critical chain start: gi0 slice 0, GH0(0), cell0(0)
    tf32_gemm1_kernel<<<dim3(CT_, RT_R), 256, SMEM_BYTES, s_hi>>>(
        xp, Wi0p, bi, gi0);
    tf32_gemm1_kernel<<<dim3(CT_, RT_R), 256, SMEM_BYTES, s_hi>>>(
        h0pb[1], Wh0p, bh, gh0);
    gru_cell0<<<MR, 128, 0, s_hi>>>(gi0, 0, gh0, h0s,
                                    (uint32_t*)h0pb[0], gamma, beta);
    cudaEventRecord(ev_h0[0], s_hi);

    for (int t = 0; t < T_; t++) {
        // --- layer-1 work for step t (lags on s_L1) ---
        cudaStreamWaitEvent(s_L1, ev_h0[t], 0);
        tf32_gemm2_kernel<<<dim3(CT_, RT_R, 2), 256, SMEM_BYTES, s_L1>>>(
            h0pb[t & 1], Wi1p, bi + G_, gi1,
            h1p,         Wh1p, bh + G_, gh1);
        cudaEventRecord(ev_gi1[t], s_L1);
        gru_cell1<<<MR, 128, 0, s_L1>>>(gi1, gh1, h1s, (uint32_t*)h1p,
                                        gamma, beta, out, t);

        // --- layer-0 critical chain: produce cell0(t+1) ---
        if (t < T_ - 1) {
            tf32_gemm1_kernel<<<dim3(CT_, RT_R), 256, SMEM_BYTES, s_hi>>>(
                h0pb[t & 1], Wh0p, bh, gh0);
            cudaStreamWaitEvent(s_hi, ev_gi0[t + 1], 0);
            if (t >= 1)
                cudaStreamWaitEvent(s_hi, ev_gi1[t - 1], 0);  // h0p reuse safety
            gru_cell0<<<MR, 128, 0, s_hi>>>(gi0, t + 1, gh0, h0s,
                                            (uint32_t*)h0pb[(t + 1) & 1],
                                            gamma, beta);
            cudaEventRecord(ev_h0[t + 1], s_hi);
        }
    }

    // join all streams back to stream 0
    cudaEventRecord(ev_hi_done, s_hi);
    cudaEventRecord(ev_L1_done, s_L1);
    cudaStreamWaitEvent(0, ev_hi_done, 0);
    cudaStreamWaitEvent(0, ev_L1_done, 0);

    long long need = (long long)MB_ * D_ + (long long)2 * MR * D_;
    if ((long long)out_size >= need) {
        int tot = 2 * MR * D_;
        write_hidden_kernel<<<(tot + 255) / 256, 256>>>(h0s, h1s,
                                                        out + (size_t)MB_ * D_);
    }
}

// round 11
// speedup vs baseline: 2.2743x; 1.8812x over previous
#include <cuda_runtime.h>
#include <cuda_bf16.h>
#include <math.h>
#include <stdint.h>

// GraphRNN: 2-layer LayerNorm-GRU scan. B=16, T=24, N=207, D=512, G=1536.
// R11: 3x-split GEMMs moved from tf32-k8 to bf16-k16 HMMA (same instruction
//      cost, 2x MACs -> HMMA count halves). Pre-split bf16 hi/lo fragment-
//      packed operands; 128x64 tiles @ 3 CTAs/SM; R10 stream structure.
namespace {
constexpr int B_ = 16, T_ = 24, N_ = 207, D_ = 512, G_ = 1536;
constexpr int MR  = B_ * N_;        // 3312 rows per timestep
constexpr int MRP = 3328;           // padded: 26*128
constexpr int MB_ = B_ * T_ * N_;   // 79488

constexpr int BK = 16;              // k-chunk (one k16 MMA per chunk)
constexpr int NCHUNK = D_ / BK;     // 32
constexpr int CT_ = G_ / 64;        // 24 col-tiles of 64
constexpr int RT_R = MRP / 128;     // 26 row-tiles per timestep

// A per (rowtile, chunk): 8 mg * 32 lanes hi + same lo = 512 quads = 8KB
// B per (coltile64, chunk): 8 g * 32 lanes = 256 quads (bh0,bh1,bl0,bl1) = 4KB
constexpr int A_Q = 512, B_Q = 256;
constexpr int STAGE_Q = A_Q + B_Q;  // 768 quads = 12KB
constexpr int STAGES = 3;
constexpr int SMEM_BYTES = STAGES * STAGE_Q * 16;  // 36864

constexpr size_t WQ_PER_W = (size_t)CT_ * NCHUNK * B_Q;   // 196608
constexpr size_t HQ  = (size_t)RT_R * NCHUNK * A_Q;       // packed rows / t
constexpr size_t XQ  = (size_t)T_ * HQ;
}

// ---------------- scratch (device globals; zero-initialized) ----------------
__device__ float g_gi0[(size_t)T_ * MRP * G_];   // t-major
__device__ float g_gh0[(size_t)MRP * G_];
__device__ float g_gi1[(size_t)MRP * G_];
__device__ float g_gh1[(size_t)MRP * G_];
__device__ float g_h0s[(size_t)MRP * D_];
__device__ float g_h1s[(size_t)MRP * D_];
__device__ uint4 g_h0p[2 * HQ];                  // double-buffered (parity t&1)
__device__ uint4 g_h1p[HQ];
__device__ uint4 g_xp[XQ];                       // t-major packed x
__device__ uint4 g_Wp[4 * WQ_PER_W];

// ---------------- helpers ----------------
__device__ __forceinline__ uint32_t smem_u32(const void* p) {
    uint32_t a;
    asm("{ .reg .u64 t; cvta.to.shared.u64 t, %1; cvt.u32.u64 %0, t; }"
        : "=r"(a) : "l"(p));
    return a;
}
#define CP_ASYNC16(dst, src) \
    asm volatile("cp.async.cg.shared.global [%0], [%1], 16;" :: "r"(dst), "l"(src))
#define CP_COMMIT() asm volatile("cp.async.commit_group;" ::: "memory")
template <int N>
__device__ __forceinline__ void cp_wait() {
    asm volatile("cp.async.wait_group %0;" :: "n"(N) : "memory");
}

// bf16 hi/lo split of a float
__device__ __forceinline__ void split_bf16(float x, uint16_t& hi, uint16_t& lo) {
    __nv_bfloat16 h = __float2bfloat16_rn(x);
    float hf = __bfloat162float(h);
    __nv_bfloat16 l = __float2bfloat16_rn(x - hf);
    hi = *reinterpret_cast<uint16_t*>(&h);
    lo = *reinterpret_cast<uint16_t*>(&l);
}
__device__ __forceinline__ uint32_t pack2(uint16_t a, uint16_t b) {
    return (uint32_t)a | ((uint32_t)b << 16);   // low = first (lower k)
}

#define MMA_BF16(d, a, b0, b1)                                              \
    asm volatile("mma.sync.aligned.m16n8k16.row.col.f32.bf16.bf16.f32 "     \
        "{%0,%1,%2,%3}, {%4,%5,%6,%7}, {%8,%9}, {%0,%1,%2,%3};"             \
        : "+f"((d)[0]), "+f"((d)[1]), "+f"((d)[2]), "+f"((d)[3])            \
        : "r"((a)[0]), "r"((a)[1]), "r"((a)[2]), "r"((a)[3]),               \
          "r"(b0), "r"(b1))

// ---------------------------------------------------------------------------
// Packed-activation writer. A layout per (rowtile rt, chunk ch): 512 quads,
// hi quad at mg*32+lane, lo at +256. Quad = (a0,a1,a2,a3) of the m16k16
// bf16-pair fragment. Writer covers 4 consecutive d values of one row.
// ---------------------------------------------------------------------------
__device__ __forceinline__ void write_packed_bf16(uint32_t* Ap, int m, int d0,
                                                  const float* y) {
    int rt = m >> 7, mrow = m & 127;
    int mg = mrow >> 4, rr = mrow & 15;
    int ch = d0 >> 4, kd = d0 & 15;          // kd in {0,4,8,12}
    int khalf = kd >> 3;                      // 0: a0/a1, 1: a2/a3
    int tgb = (kd & 7) >> 1;                  // 0 or 2
    int s = (rr >> 3) + 2 * khalf;            // reg slot in quad
    size_t base = ((size_t)rt * NCHUNK + ch) * A_Q;
    uint16_t h0, l0, h1, l1;
#pragma unroll
    for (int j = 0; j < 2; j++) {
        split_bf16(y[2 * j],     h0, l0);
        split_bf16(y[2 * j + 1], h1, l1);
        int lane = (rr & 7) * 4 + tgb + j;
        size_t qhi = base + (size_t)mg * 32 + lane;
        Ap[qhi * 4 + s]               = pack2(h0, h1);
        Ap[(qhi + 256) * 4 + s]       = pack2(l0, l1);
    }
}

// ---------------------------------------------------------------------------
// GEMM core (128x64 C tile), pure LDS.128 + bf16 k16 HMMA.
// 256 thr, 8 warps (warpM 0..3 x warpN 0..1, 32 cols each).
// ---------------------------------------------------------------------------
__device__ __forceinline__ void load_stage(uint32_t sS, const uint4* __restrict__ Aq,
                                           const uint4* __restrict__ Bq,
                                           int ch, int tid) {
    const uint4* a = Aq + (size_t)ch * A_Q;
    const uint4* b = Bq + (size_t)ch * B_Q;
#pragma unroll
    for (int i = 0; i < 2; i++) {
        int s = tid + i * 256;
        CP_ASYNC16(sS + (uint32_t)s * 16u, a + s);
    }
    CP_ASYNC16(sS + (uint32_t)(A_Q + tid) * 16u, b + tid);
}

__device__ __forceinline__ void bf16_gemm_core(const uint4* __restrict__ Ap,
                                               const uint4* __restrict__ Wp,
                                               const float* __restrict__ bias,
                                               float* __restrict__ C) {
    extern __shared__ uint4 smq[];

    const int tid  = threadIdx.x;
    const int lane = tid & 31, warp = tid >> 5;
    const int warpM = warp & 3, warpN = warp >> 2;
    const int r  = lane >> 2;
    const int qk = lane & 3;

    const uint4* Aq = Ap + (size_t)blockIdx.y * (NCHUNK * A_Q);
    const uint4* Bq = Wp + (size_t)blockIdx.x * (NCHUNK * B_Q);

    float acc[2][4][4];
#pragma unroll
    for (int mt = 0; mt < 2; mt++)
#pragma unroll
        for (int nt = 0; nt < 4; nt++)
#pragma unroll
            for (int i = 0; i < 4; i++) acc[mt][nt][i] = 0.f;

    uint32_t sb = smem_u32(smq);
    load_stage(sb, Aq, Bq, 0, tid);
    CP_COMMIT();
    load_stage(sb + STAGE_Q * 16, Aq, Bq, 1, tid);
    CP_COMMIT();

    for (int ch = 0; ch < NCHUNK; ch++) {
        if (ch < NCHUNK - 1) cp_wait<1>(); else cp_wait<0>();
        __syncthreads();
        if (ch + 2 < NCHUNK) {
            load_stage(sb + ((ch + 2) % STAGES) * (STAGE_Q * 16), Aq, Bq, ch + 2, tid);
            CP_COMMIT();
        }
        const uint4* As = smq + (size_t)(ch % STAGES) * STAGE_Q;
        const uint4* Bs = As + A_Q;

        uint4 ah[2], al[2];
#pragma unroll
        for (int mt = 0; mt < 2; mt++) {
            int mg = warpM * 2 + mt;
            ah[mt] = As[mg * 32 + lane];
            al[mt] = As[mg * 32 + lane + 256];
        }
        uint4 bf[4];
#pragma unroll
        for (int j = 0; j < 4; j++) {
            int g = warpN * 4 + j;
            bf[j] = Bs[g * 32 + lane];
        }
        // pass 1: al * bh
#pragma unroll
        for (int j = 0; j < 4; j++)
#pragma unroll
            for (int mt = 0; mt < 2; mt++)
                MMA_BF16(acc[mt][j], ((const uint32_t*)&al[mt]),
                         bf[j].x, bf[j].y);
        // pass 2: ah * bl
#pragma unroll
        for (int j = 0; j < 4; j++)
#pragma unroll
            for (int mt = 0; mt < 2; mt++)
                MMA_BF16(acc[mt][j], ((const uint32_t*)&ah[mt]),
                         bf[j].z, bf[j].w);
        // pass 3: ah * bh
#pragma unroll
        for (int j = 0; j < 4; j++)
#pragma unroll
            for (int mt = 0; mt < 2; mt++)
                MMA_BF16(acc[mt][j], ((const uint32_t*)&ah[mt]),
                         bf[j].x, bf[j].y);
    }

    const int brow = blockIdx.y * 128;
    const int bcol = blockIdx.x * 64;
    const int q2 = qk * 2;
#pragma unroll
    for (int mt = 0; mt < 2; mt++) {
        const int row0 = brow + warpM * 32 + mt * 16 + r;
#pragma unroll
        for (int nt = 0; nt < 4; nt++) {
            const int col = bcol + warpN * 32 + nt * 8 + q2;
            const float2 bv = *reinterpret_cast<const float2*>(bias + col);
            float2 v0 = make_float2(acc[mt][nt][0] + bv.x, acc[mt][nt][1] + bv.y);
            float2 v1 = make_float2(acc[mt][nt][2] + bv.x, acc[mt][nt][3] + bv.y);
            *reinterpret_cast<float2*>(C + (size_t)row0 * G_ + col) = v0;
            *reinterpret_cast<float2*>(C + (size_t)(row0 + 8) * G_ + col) = v1;
        }
    }
}

__global__ void __launch_bounds__(256, 3)
bf16_gemm1_kernel(const uint4* __restrict__ Ap, const uint4* __restrict__ Wp,
                  const float* __restrict__ bias, float* __restrict__ C) {
    bf16_gemm_core(Ap, Wp, bias, C);
}

// two GEMMs in one launch (layer-1: GI1 and GH1)
__global__ void __launch_bounds__(256, 3)
bf16_gemm2_kernel(const uint4* A0, const uint4* P0, const float* b0, float* C0,
                  const uint4* A1, const uint4* P1, const float* b1, float* C1) {
    const uint4* A; const uint4* P; const float* bias; float* C;
    if (blockIdx.z == 0) { A = A0; P = P0; bias = b0; C = C0; }
    else                 { A = A1; P = P1; bias = b1; C = C1; }
    bf16_gemm_core(A, P, bias, C);
}

// ---------------------------------------------------------------------------
// Weight prepack (BK=16, 64-col tiles): quad e = g*32+lane holds
// (bh0, bh1, bl0, bl1): col = ct*64 + g*8 + (lane>>2), tg = lane&3,
// b0 pair k = 2tg,2tg+1 ; b1 pair k = 2tg+8,2tg+9 (within chunk).
// ---------------------------------------------------------------------------
__global__ void prepack_kernel(const float* __restrict__ Wi,
                               const float* __restrict__ Wh,
                               uint4* __restrict__ Wp) {
    __shared__ float tile[16][64];
    const int ct = blockIdx.x, ch = blockIdx.y, z = blockIdx.z;
    const float* src = (z < 2 ? Wi : Wh) + (size_t)(z & 1) * D_ * G_;
    const int tid = threadIdx.x;

#pragma unroll
    for (int i = 0; i < 4; i++) {
        int s = tid + i * 256;
        int kk = s >> 6, n = s & 63;
        tile[kk][n] = src[(size_t)(ch * BK + kk) * G_ + ct * 64 + n];
    }
    __syncthreads();

    uint4* dst = Wp + ((size_t)z * CT_ + ct) * (NCHUNK * B_Q) + (size_t)ch * B_Q;
    if (tid < 256) {
        int lane = tid & 31, g = tid >> 5;
        int nl = g * 8 + (lane >> 2);
        int tg = lane & 3;
        uint16_t h0a, l0a, h0b, l0b, h1a, l1a, h1b, l1b;
        split_bf16(tile[2 * tg][nl],     h0a, l0a);
        split_bf16(tile[2 * tg + 1][nl], h0b, l0b);
        split_bf16(tile[2 * tg + 8][nl], h1a, l1a);
        split_bf16(tile[2 * tg + 9][nl], h1b, l1b);
        uint4 q;
        q.x = pack2(h0a, h0b);   // bh0
        q.y = pack2(h1a, h1b);   // bh1
        q.z = pack2(l0a, l0b);   // bl0
        q.w = pack2(l1a, l1b);   // bl1
        dst[tid] = q;
    }
}

// ---------------------------------------------------------------------------
// x prepack: x row (b,t,n) -> t-major packed row t*MRP + b*N + n
// ---------------------------------------------------------------------------
__global__ void xpack_kernel(const float* __restrict__ x, uint4* __restrict__ xp) {
    int min_ = blockIdx.x;              // (b*T+t)*N + n
    int n = min_ % N_;
    int t = (min_ / N_) % T_;
    int b = min_ / (N_ * T_);
    int m = t * MRP + b * N_ + n;
    int tid = threadIdx.x;
    float4 v = reinterpret_cast<const float4*>(x + (size_t)min_ * D_)[tid];
    float y[4] = { v.x, v.y, v.z, v.w };
    write_packed_bf16((uint32_t*)xp, m, tid * 4, y);
}

// ---------------------------------------------------------------------------
// Fused GRU cell + LayerNorm
// ---------------------------------------------------------------------------
__device__ __forceinline__ float sigf(float v) { return 1.f / (1.f + expf(-v)); }

__device__ __forceinline__ void cell_body(const float* __restrict__ gi,
                                          const float* __restrict__ ghrow,
                                          float* __restrict__ hrow,
                                          uint32_t* __restrict__ hpack, int m,
                                          const float* __restrict__ gamma,
                                          const float* __restrict__ beta,
                                          float* __restrict__ o2) {
    const float4* gi4 = reinterpret_cast<const float4*>(gi);
    const float4* gh4 = reinterpret_cast<const float4*>(ghrow);
    float4* h4 = reinterpret_cast<float4*>(hrow);
    int tid = threadIdx.x;

    float4 ir = gi4[tid], iz = gi4[128 + tid], inn = gi4[256 + tid];
    float4 hr = gh4[tid], hz = gh4[128 + tid], hn = gh4[256 + tid];
    float4 hv = h4[tid];

    float o[4];
    {
        float rr, z, nv;
        rr = sigf(ir.x + hr.x); z = sigf(iz.x + hz.x); nv = tanhf(inn.x + rr * hn.x);
        o[0] = nv + z * (hv.x - nv);
        rr = sigf(ir.y + hr.y); z = sigf(iz.y + hz.y); nv = tanhf(inn.y + rr * hn.y);
        o[1] = nv + z * (hv.y - nv);
        rr = sigf(ir.z + hr.z); z = sigf(iz.z + hz.z); nv = tanhf(inn.z + rr * hn.z);
        o[2] = nv + z * (hv.z - nv);
        rr = sigf(ir.w + hr.w); z = sigf(iz.w + hz.w); nv = tanhf(inn.w + rr * hn.w);
        o[3] = nv + z * (hv.w - nv);
    }
    float s = o[0] + o[1] + o[2] + o[3];
    float s2 = o[0]*o[0] + o[1]*o[1] + o[2]*o[2] + o[3]*o[3];
#pragma unroll
    for (int off = 16; off > 0; off >>= 1) {
        s  += __shfl_xor_sync(0xffffffffu, s,  off);
        s2 += __shfl_xor_sync(0xffffffffu, s2, off);
    }
    __shared__ float sh[4], sh2[4];
    int w = tid >> 5;
    if ((tid & 31) == 0) { sh[w] = s; sh2[w] = s2; }
    __syncthreads();
    s  = sh[0]  + sh[1]  + sh[2]  + sh[3];
    s2 = sh2[0] + sh2[1] + sh2[2] + sh2[3];
    float mu  = s * (1.f / D_);
    float var = s2 * (1.f / D_) - mu * mu;
    float inv = rsqrtf(var + 1e-5f);

    const float4 g4 = reinterpret_cast<const float4*>(gamma)[tid];
    const float4 b4 = reinterpret_cast<const float4*>(beta)[tid];
    float y[4];
    y[0] = (o[0] - mu) * inv * g4.x + b4.x;
    y[1] = (o[1] - mu) * inv * g4.y + b4.y;
    y[2] = (o[2] - mu) * inv * g4.z + b4.z;
    y[3] = (o[3] - mu) * inv * g4.w + b4.w;
    h4[tid] = make_float4(y[0], y[1], y[2], y[3]);
    write_packed_bf16(hpack, m, tid * 4, y);
    if (o2) reinterpret_cast<float4*>(o2)[tid] =
        make_float4(y[0], y[1], y[2], y[3]);
}

// layer-0 cell: gi0 t-major slice; writes h0s + packed h0p (given parity buf)
__global__ void __launch_bounds__(128)
gru_cell0(const float* __restrict__ gi0, int t,
          const float* __restrict__ gh, float* __restrict__ h,
          uint32_t* __restrict__ hpack,
          const float* __restrict__ gamma, const float* __restrict__ beta) {
    int m = blockIdx.x;
    const float* gi = gi0 + ((size_t)t * MRP + m) * G_;
    cell_body(gi, gh + (size_t)m * G_, h + (size_t)m * D_, hpack, m,
              gamma, beta, nullptr);
}

// layer-1 cell: writes out[:, t] + h1s + h1p
__global__ void __launch_bounds__(128)
gru_cell1(const float* __restrict__ gi1, const float* __restrict__ gh1,
          float* __restrict__ h1s, uint32_t* __restrict__ h1p,
          const float* __restrict__ gamma, const float* __restrict__ beta,
          float* __restrict__ out, int t) {
    int m = blockIdx.x;
    int b = m / N_, n = m % N_;
    float* o2 = out + ((size_t)(b * T_ + t) * N_ + n) * D_;
    cell_body(gi1 + (size_t)m * G_, gh1 + (size_t)m * G_,
              h1s + (size_t)m * D_, h1p, m, gamma + D_, beta + D_, o2);
}

// ---------------------------------------------------------------------------
__global__ void init_h_kernel(const float* __restrict__ h0,
                              float* __restrict__ h0s, float* __restrict__ h1s,
                              uint32_t* __restrict__ h0p_init,
                              uint32_t* __restrict__ h1p) {
    int row = blockIdx.x;
    int n = row % N_;
    int l = (row / N_) % 2;
    int b = row / (2 * N_);
    int tid = threadIdx.x;
    int m = b * N_ + n;
    float4 v = reinterpret_cast<const float4*>(h0 + (size_t)row * D_)[tid];
    float* hs = (l == 0) ? h0s : h1s;
    reinterpret_cast<float4*>(hs + (size_t)m * D_)[tid] = v;
    float y[4] = { v.x, v.y, v.z, v.w };
    write_packed_bf16((l == 0) ? h0p_init : h1p, m, tid * 4, y);
}

__global__ void write_hidden_kernel(const float* __restrict__ h0s,
                                    const float* __restrict__ h1s,
                                    float* __restrict__ dst) {
    int i = blockIdx.x * blockDim.x + threadIdx.x;
    if (i >= 2 * MR * D_) return;
    int d = i % D_;
    int r = i / D_;
    int n = r % N_; r /= N_;
    int l = r % 2;
    int b = r / 2;
    const float* src = (l == 0) ? h0s : h1s;
    dst[i] = src[((size_t)b * N_ + n) * D_ + d];
}

// ---------------------------------------------------------------------------
extern "C" void kernel_launch(void* const* d_in, const int* in_sizes, int n_in,
                              void* d_out, int out_size) {
    (void)in_sizes; (void)n_in;
    const float* x     = (const float*)d_in[0];
    const float* h0    = (const float*)d_in[1];
    const float* Wi    = (const float*)d_in[2];
    const float* bi    = (const float*)d_in[3];
    const float* Wh    = (const float*)d_in[4];
    const float* bh    = (const float*)d_in[5];
    const float* gamma = (const float*)d_in[6];
    const float* beta  = (const float*)d_in[7];
    float* out = (float*)d_out;

    float *gi0, *gh0, *gi1, *gh1, *h0s, *h1s;
    uint4 *h0p, *h1p, *xp, *Wp;
    cudaGetSymbolAddress((void**)&gi0, g_gi0);
    cudaGetSymbolAddress((void**)&gh0, g_gh0);
    cudaGetSymbolAddress((void**)&gi1, g_gi1);
    cudaGetSymbolAddress((void**)&gh1, g_gh1);
    cudaGetSymbolAddress((void**)&h0s, g_h0s);
    cudaGetSymbolAddress((void**)&h1s, g_h1s);
    cudaGetSymbolAddress((void**)&h0p, g_h0p);
    cudaGetSymbolAddress((void**)&h1p, g_h1p);
    cudaGetSymbolAddress((void**)&xp,  g_xp);
    cudaGetSymbolAddress((void**)&Wp,  g_Wp);

    cudaFuncSetAttribute(bf16_gemm1_kernel,
                         cudaFuncAttributeMaxDynamicSharedMemorySize, SMEM_BYTES);
    cudaFuncSetAttribute(bf16_gemm2_kernel,
                         cudaFuncAttributeMaxDynamicSharedMemorySize, SMEM_BYTES);

    // lazy-init streams/events
    static cudaStream_t s_hi = nullptr, s_L1 = nullptr, s_bg = nullptr;
    static cudaEvent_t ev_fork, ev_hi_done, ev_L1_done;
    static cudaEvent_t ev_gi0[T_], ev_h0[T_], ev_gi1[T_];
    if (!s_hi) {
        int lo = 0, hi = 0;
        cudaDeviceGetStreamPriorityRange(&lo, &hi);
        cudaStreamCreateWithPriority(&s_hi, cudaStreamNonBlocking, hi);
        cudaStreamCreateWithPriority(&s_L1, cudaStreamNonBlocking, lo);
        cudaStreamCreateWithPriority(&s_bg, cudaStreamNonBlocking, lo);
        cudaEventCreateWithFlags(&ev_fork,    cudaEventDisableTiming);
        cudaEventCreateWithFlags(&ev_hi_done, cudaEventDisableTiming);
        cudaEventCreateWithFlags(&ev_L1_done, cudaEventDisableTiming);
        for (int i = 0; i < T_; i++) {
            cudaEventCreateWithFlags(&ev_gi0[i], cudaEventDisableTiming);
            cudaEventCreateWithFlags(&ev_h0[i],  cudaEventDisableTiming);
            cudaEventCreateWithFlags(&ev_gi1[i], cudaEventDisableTiming);
        }
    }

    const uint4* Wi0p = Wp;
    const uint4* Wi1p = Wp + WQ_PER_W;
    const uint4* Wh0p = Wp + 2 * WQ_PER_W;
    const uint4* Wh1p = Wp + 3 * WQ_PER_W;
    uint4* h0pb[2] = { h0p, h0p + HQ };

    // ---- prologue on stream 0 ----
    prepack_kernel<<<dim3(CT_, NCHUNK, 4), 256>>>(Wi, Wh, Wp);
    init_h_kernel<<<2 * MR, 128>>>(h0, h0s, h1s,
                                   (uint32_t*)h0pb[1], (uint32_t*)h1p);
    xpack_kernel<<<MB_, 128>>>(x, xp);

    cudaEventRecord(ev_fork, 0);
    cudaStreamWaitEvent(s_bg, ev_fork, 0);
    cudaStreamWaitEvent(s_hi, ev_fork, 0);

    // background: gi0 slices 1..T-1
    for (int t = 1; t < T_; t++) {
        bf16_gemm1_kernel<<<dim3(CT_, RT_R), 256, SMEM_BYTES, s_bg>>>(
            xp + (size_t)t * HQ, Wi0p, bi, gi0 + (size_t)t * MRP * G_);
        cudaEventRecord(ev_gi0[t], s_bg);
    }

    // critical chain start: gi0 slice 0, GH0(0), cell0(0)
    bf16_gemm1_kernel<<<dim3(CT_, RT_R), 256, SMEM_BYTES, s_hi>>>(
        xp, Wi0p, bi, gi0);
    bf16_gemm1_kernel<<<dim3(CT_, RT_R), 256, SMEM_BYTES, s_hi>>>(
        h0pb[1], Wh0p, bh, gh0);
    gru_cell0<<<MR, 128, 0, s_hi>>>(gi0, 0, gh0, h0s,
                                    (uint32_t*)h0pb[0], gamma, beta);
    cudaEventRecord(ev_h0[0], s_hi);

    for (int t = 0; t < T_; t++) {
        // --- layer-1 work for step t (lags on s_L1) ---
        cudaStreamWaitEvent(s_L1, ev_h0[t], 0);
        bf16_gemm2_kernel<<<dim3(CT_, RT_R, 2), 256, SMEM_BYTES, s_L1>>>(
            h0pb[t & 1], Wi1p, bi + G_, gi1,
            h1p,         Wh1p, bh + G_, gh1);
        cudaEventRecord(ev_gi1[t], s_L1);
        gru_cell1<<<MR, 128, 0, s_L1>>>(gi1, gh1, h1s, (uint32_t*)h1p,
                                        gamma, beta, out, t);

        // --- layer-0 critical chain: produce cell0(t+1) ---
        if (t < T_ - 1) {
            bf16_gemm1_kernel<<<dim3(CT_, RT_R), 256, SMEM_BYTES, s_hi>>>(
                h0pb[t & 1], Wh0p, bh, gh0);
            cudaStreamWaitEvent(s_hi, ev_gi0[t + 1], 0);
            if (t >= 1)
                cudaStreamWaitEvent(s_hi, ev_gi1[t - 1], 0);  // h0p reuse safety
            gru_cell0<<<MR, 128, 0, s_hi>>>(gi0, t + 1, gh0, h0s,
                                            (uint32_t*)h0pb[(t + 1) & 1],
                                            gamma, beta);
            cudaEventRecord(ev_h0[t + 1], s_hi);
        }
    }

    // join all streams back to stream 0
    cudaEventRecord(ev_hi_done, s_hi);
    cudaEventRecord(ev_L1_done, s_L1);
    cudaStreamWaitEvent(0, ev_hi_done, 0);
    cudaStreamWaitEvent(0, ev_L1_done, 0);

    long long need = (long long)MB_ * D_ + (long long)2 * MR * D_;
    if ((long long)out_size >= need) {
        int tot = 2 * MR * D_;
        write_hidden_kernel<<<(tot + 255) / 256, 256>>>(h0s, h1s,
                                                        out + (size_t)MB_ * D_);
    }
}